// round 2
// baseline (speedup 1.0000x reference)
#include <cuda_runtime.h>
#include <cuda_bf16.h>
#include <math.h>

namespace {

constexpr int NVc = 32;   // x dim
constexpr int MCc = 24;   // constraint rows in A
constexpr int MHc = 20;   // hard rows
constexpr int ITc = 200;  // ADMM iterations

// per-warp shared layout (floats)
constexpr int OFF_A = 0;            // A: 24 rows, stride 36
constexpr int OFF_M = 864;          // M workspace: 36 x 36
constexpr int OFF_T = 2160;         // t buffer (32)
constexpr int OFF_R = 2192;         // rhs (40)
constexpr int OFF_U = 2232;         // u (40)
constexpr int WARPF = 2304;         // 9216 bytes per warp

__device__ __forceinline__ float d4(float4 a, float4 b) {
    return a.x * b.x + a.y * b.y + a.z * b.z + a.w * b.w;
}

// In-place warp-parallel Gauss-Jordan inverse of SPD n x n, row stride 36.
template <int n>
__device__ __forceinline__ void gj_inv(float* Mw, int tid) {
#pragma unroll 1
    for (int k = 0; k < n; k++) {
        float piv = 1.0f / Mw[k * 36 + k];
        __syncwarp();
#pragma unroll 1
        for (int j = tid; j < n; j += 32)
            Mw[k * 36 + j] = (j == k) ? piv : Mw[k * 36 + j] * piv;
        __syncwarp();
#pragma unroll 1
        for (int i = tid; i < n; i += 32) {
            if (i == k) continue;
            float f = Mw[i * 36 + k];
            const float4* rk = reinterpret_cast<const float4*>(Mw + k * 36);
            float4*       ri = reinterpret_cast<float4*>(Mw + i * 36);
#pragma unroll
            for (int q = 0; q < n / 4; q++) {
                float4 a = ri[q];
                float4 bq = rk[q];
                a.x = fmaf(-f, bq.x, a.x);
                a.y = fmaf(-f, bq.y, a.y);
                a.z = fmaf(-f, bq.z, a.z);
                a.w = fmaf(-f, bq.w, a.w);
                ri[q] = a;
            }
            Mw[i * 36 + k] = -f * piv;
        }
        __syncwarp();
    }
}

__global__ void __launch_bounds__(128, 4)
fw_kernel(const float* __restrict__ x_raw, const float* __restrict__ Ain,
          const float* __restrict__ bin, const float* __restrict__ W1,
          const float* __restrict__ b1v, const float* __restrict__ w2,
          float* __restrict__ out, int P)
{
    __shared__ __align__(16) float smem_all[4 * WARPF];
    const int tid = threadIdx.x & 31;
    const int wid = threadIdx.x >> 5;
    const int p = blockIdx.x * 4 + wid;
    if (p >= P) return;
    float* sw = smem_all + wid * WARPF;

    // ------------------------------------------------------------------
    // Load A (smem rows + register column), b, x_raw
    // ------------------------------------------------------------------
    float Acol[MCc];
    {
        const float* Ap = Ain + (size_t)p * (MCc * NVc);
#pragma unroll
        for (int r = 0; r < MCc; r++) {
            float v = Ap[r * NVc + tid];
            sw[OFF_A + r * 36 + tid] = v;
            Acol[r] = v;
        }
    }
    const float b_own = (tid < MCc) ? bin[(size_t)p * MCc + tid] : 0.0f;
    const float xr = x_raw[(size_t)p * NVc + tid];
    __syncwarp();

    // ------------------------------------------------------------------
    // Anchor M = [[A^T A + 2I, -A_soft^T], [-A_soft, 4I]]  (36x36)
    // row tid (x-rows 0..31) built in registers via rank-1 updates
    // ------------------------------------------------------------------
    {
        float mr[36];
#pragma unroll
        for (int e = 0; e < 36; e++) mr[e] = 0.0f;
#pragma unroll
        for (int r = 0; r < MCc; r++) {
            const float4* ar = reinterpret_cast<const float4*>(sw + OFF_A + r * 36);
            float a = Acol[r];
#pragma unroll
            for (int q = 0; q < 8; q++) {
                float4 v = ar[q];
                mr[4 * q + 0] = fmaf(a, v.x, mr[4 * q + 0]);
                mr[4 * q + 1] = fmaf(a, v.y, mr[4 * q + 1]);
                mr[4 * q + 2] = fmaf(a, v.z, mr[4 * q + 2]);
                mr[4 * q + 3] = fmaf(a, v.w, mr[4 * q + 3]);
            }
        }
#pragma unroll
        for (int k = 0; k < 4; k++) mr[32 + k] = -Acol[MHc + k];
        float4* md = reinterpret_cast<float4*>(sw + OFF_M + tid * 36);
#pragma unroll
        for (int q = 0; q < 9; q++)
            md[q] = make_float4(mr[4 * q], mr[4 * q + 1], mr[4 * q + 2], mr[4 * q + 3]);
        sw[OFF_M + tid * 36 + tid] += 2.0f;  // + 2I on x-block diagonal
    }
    __syncwarp();
    if (tid < 4) {  // slack rows 32..35
        float* md = sw + OFF_M + (32 + tid) * 36;
        const float* as = sw + OFF_A + (MHc + tid) * 36;
#pragma unroll
        for (int e = 0; e < 32; e++) md[e] = -as[e];
#pragma unroll
        for (int j = 0; j < 4; j++) md[32 + j] = (j == tid) ? 4.0f : 0.0f;
    }
    __syncwarp();

    gj_inv<36>(sw + OFF_M, tid);

    float minv[36];
    {
        const float4* ms = reinterpret_cast<const float4*>(sw + OFF_M + tid * 36);
#pragma unroll
        for (int q = 0; q < 9; q++) {
            float4 v = ms[q];
            minv[4 * q] = v.x; minv[4 * q + 1] = v.y; minv[4 * q + 2] = v.z; minv[4 * q + 3] = v.w;
        }
    }

    // ------------------------------------------------------------------
    // Anchor ADMM. Row ownership: rows 0..27 -> lanes 0..27 (y1,t1);
    // rows 28..59 (-I_n block) -> lane tid (y3,t3). t3 = z - y per row.
    // ------------------------------------------------------------------
    float y1 = 0.0f, t1 = 0.0f, y3 = 0.0f, t3 = 0.0f, u_own = 0.0f;
    const float h1 = (tid < MCc) ? b_own : 0.0f;  // rows 24..27 have h=0
#pragma unroll 1
    for (int it = 0; it <= ITc; ++it) {
        if (tid < 28) sw[OFF_T + tid] = t1;
        __syncwarp();
        // rhs_x[tid] = x_raw + sum_r A[r][tid] t[r] - t[28+tid]; rhs_s[k] = -t[20+k]-t[24+k]
        {
            const float4* t4 = reinterpret_cast<const float4*>(sw + OFF_T);
            float a0 = xr, a1 = 0.0f;
#pragma unroll
            for (int q = 0; q < 6; q++) {
                float4 tv = t4[q];
                float s = Acol[4 * q] * tv.x + Acol[4 * q + 1] * tv.y
                        + Acol[4 * q + 2] * tv.z + Acol[4 * q + 3] * tv.w;
                if (q & 1) a1 += s; else a0 += s;
            }
            sw[OFF_R + tid] = a0 + a1 - t3;
            if (tid >= 28) {
                int k = tid - 28;
                sw[OFF_R + 32 + k] = -sw[OFF_T + MHc + k] - sw[OFF_T + MCc + k];
            }
        }
        __syncwarp();
        // u = Minv rhs  (row tid from regs; rows 32..35 by lanes 28..31 from smem)
        {
            const float4* r4 = reinterpret_cast<const float4*>(sw + OFF_R);
            const float4* m2 = reinterpret_cast<const float4*>(sw + OFF_M + (tid + 4) * 36);
            float a0 = 0.0f, a1 = 0.0f, bx = 0.0f;
#pragma unroll
            for (int q = 0; q < 9; q++) {
                float4 rv = r4[q];
                float s = minv[4 * q] * rv.x + minv[4 * q + 1] * rv.y
                        + minv[4 * q + 2] * rv.z + minv[4 * q + 3] * rv.w;
                if (q & 1) a1 += s; else a0 += s;
                if (tid >= 28) bx += d4(m2[q], rv);
            }
            u_own = a0 + a1;
            sw[OFF_U + tid] = u_own;
            if (tid >= 28) sw[OFF_U + 32 + (tid - 28)] = bx;
        }
        __syncwarp();
        if (it == ITc) break;
        // Gu, then z/y/t updates in registers
        {
            const float4* u4 = reinterpret_cast<const float4*>(sw + OFF_U);
            const float4* ar = reinterpret_cast<const float4*>(sw + OFF_A + tid * 36);
            float r0 = 0.0f, r1 = 0.0f;
#pragma unroll
            for (int q = 0; q < 8; q++) {
                float4 uv = u4[q];
                if (tid < MCc) {
                    float s = d4(ar[q], uv);
                    if (q & 1) r1 += s; else r0 += s;
                }
            }
            float rowdot = r0 + r1;
            float4 us = u4[8];  // u[32..35]
            float gu1;
            if (tid < MHc) {
                gu1 = rowdot;
            } else {
                int kk = (tid < MCc) ? (tid - MHc) : (tid - MCc);
                float usk = (kk == 0) ? us.x : (kk == 1) ? us.y : (kk == 2) ? us.z : us.w;
                gu1 = (tid < MCc) ? (rowdot - usk) : (-usk);
            }
            float w = gu1 + y1;
            float z = fminf(w, h1);
            y1 = w - z;
            t1 = z - y1;
            float w3 = y3 - u_own;   // Gu[28+tid] = -u[tid]
            float z3 = fminf(w3, 0.0f);
            y3 = w3 - z3;
            t3 = z3 - y3;
        }
    }
    const float xf_own = u_own;   // x_feas[tid]; full u also lives in sw[OFF_U]

    // ------------------------------------------------------------------
    // Gradient of critic: g = W1 @ (w2 * (1 - tanh^2(x W1 + b1)))
    // ------------------------------------------------------------------
    float g_own;
    {
        float vh[8];
#pragma unroll
        for (int hb = 0; hb < 8; ++hb) {
            int h = hb * 32 + tid;
            float z0 = b1v[h], z1b = 0.0f;
            const float4* x4 = reinterpret_cast<const float4*>(sw + OFF_U);
#pragma unroll
            for (int q = 0; q < 8; q++) {
                float4 xv = x4[q];
                float s = xv.x * W1[(4 * q + 0) * 256 + h] + xv.y * W1[(4 * q + 1) * 256 + h]
                        + xv.z * W1[(4 * q + 2) * 256 + h] + xv.w * W1[(4 * q + 3) * 256 + h];
                if (q & 1) z1b += s; else z0 += s;
            }
            float th = tanhf(z0 + z1b);
            vh[hb] = w2[h] * (1.0f - th * th);
        }
        // partial g per lane (over its 8 h's), coalesced W1 reads
        float gp[32];
#pragma unroll
        for (int j = 0; j < 32; j++) gp[j] = 0.0f;
#pragma unroll
        for (int hb = 0; hb < 8; ++hb) {
            int h = hb * 32 + tid;
            float v = vh[hb];
#pragma unroll
            for (int j = 0; j < 32; j++) gp[j] = fmaf(W1[j * 256 + h], v, gp[j]);
        }
        // transpose-reduce through the (now free) M workspace
        __syncwarp();
        float4* md = reinterpret_cast<float4*>(sw + OFF_M + tid * 36);
#pragma unroll
        for (int q = 0; q < 8; q++)
            md[q] = make_float4(gp[4 * q], gp[4 * q + 1], gp[4 * q + 2], gp[4 * q + 3]);
        __syncwarp();
        float gs0 = 0.0f, gs1 = 0.0f;
#pragma unroll
        for (int i = 0; i < 32; i++) {
            float v = sw[OFF_M + i * 36 + tid];
            if (i & 1) gs1 += v; else gs0 += v;
        }
        g_own = gs0 + gs1;
    }
    __syncwarp();

    // ------------------------------------------------------------------
    // LMO M = A^T A + I  (32x32)
    // ------------------------------------------------------------------
    {
        float mr[32];
#pragma unroll
        for (int e = 0; e < 32; e++) mr[e] = 0.0f;
#pragma unroll
        for (int r = 0; r < MCc; r++) {
            const float4* ar = reinterpret_cast<const float4*>(sw + OFF_A + r * 36);
            float a = Acol[r];
#pragma unroll
            for (int q = 0; q < 8; q++) {
                float4 v = ar[q];
                mr[4 * q + 0] = fmaf(a, v.x, mr[4 * q + 0]);
                mr[4 * q + 1] = fmaf(a, v.y, mr[4 * q + 1]);
                mr[4 * q + 2] = fmaf(a, v.z, mr[4 * q + 2]);
                mr[4 * q + 3] = fmaf(a, v.w, mr[4 * q + 3]);
            }
        }
        float4* md = reinterpret_cast<float4*>(sw + OFF_M + tid * 36);
#pragma unroll
        for (int q = 0; q < 8; q++)
            md[q] = make_float4(mr[4 * q], mr[4 * q + 1], mr[4 * q + 2], mr[4 * q + 3]);
        sw[OFF_M + tid * 36 + tid] += 1.0f;
    }
    __syncwarp();

    gj_inv<32>(sw + OFF_M, tid);
    {
        const float4* ms = reinterpret_cast<const float4*>(sw + OFF_M + tid * 36);
#pragma unroll
        for (int q = 0; q < 8; q++) {
            float4 v = ms[q];
            minv[4 * q] = v.x; minv[4 * q + 1] = v.y; minv[4 * q + 2] = v.z; minv[4 * q + 3] = v.w;
        }
    }

    // ------------------------------------------------------------------
    // LMO ADMM: rows 0..23 (A, h=b) on lanes 0..23; rows 24..55 (-I, h=0)
    // ------------------------------------------------------------------
    y1 = 0.0f; t1 = 0.0f; y3 = 0.0f; t3 = 0.0f;
#pragma unroll 1
    for (int it = 0; it <= ITc; ++it) {
        if (tid < MCc) sw[OFF_T + tid] = t1;
        __syncwarp();
        {
            const float4* t4 = reinterpret_cast<const float4*>(sw + OFF_T);
            float a0 = g_own, a1 = 0.0f;
#pragma unroll
            for (int q = 0; q < 6; q++) {
                float4 tv = t4[q];
                float s = Acol[4 * q] * tv.x + Acol[4 * q + 1] * tv.y
                        + Acol[4 * q + 2] * tv.z + Acol[4 * q + 3] * tv.w;
                if (q & 1) a1 += s; else a0 += s;
            }
            sw[OFF_R + tid] = a0 + a1 - t3;
        }
        __syncwarp();
        {
            const float4* r4 = reinterpret_cast<const float4*>(sw + OFF_R);
            float a0 = 0.0f, a1 = 0.0f;
#pragma unroll
            for (int q = 0; q < 8; q++) {
                float4 rv = r4[q];
                float s = minv[4 * q] * rv.x + minv[4 * q + 1] * rv.y
                        + minv[4 * q + 2] * rv.z + minv[4 * q + 3] * rv.w;
                if (q & 1) a1 += s; else a0 += s;
            }
            u_own = a0 + a1;
            sw[OFF_U + tid] = u_own;
        }
        __syncwarp();
        if (it == ITc) break;
        {
            const float4* u4 = reinterpret_cast<const float4*>(sw + OFF_U);
            const float4* ar = reinterpret_cast<const float4*>(sw + OFF_A + tid * 36);
            float r0 = 0.0f, r1 = 0.0f;
#pragma unroll
            for (int q = 0; q < 8; q++) {
                float4 uv = u4[q];
                if (tid < MCc) {
                    float s = d4(ar[q], uv);
                    if (q & 1) r1 += s; else r0 += s;
                }
            }
            float w = r0 + r1 + y1;
            float z = fminf(w, b_own);
            y1 = w - z;
            t1 = z - y1;
            float w3 = y3 - u_own;   // Gu[24+tid] = -u[tid]
            float z3 = fminf(w3, 0.0f);
            y3 = w3 - z3;
            t3 = z3 - y3;
        }
    }

    // Frank-Wolfe blend
    out[(size_t)p * NVc + tid] = 0.9f * xf_own + 0.1f * u_own;
}

}  // namespace

extern "C" void kernel_launch(void* const* d_in, const int* in_sizes, int n_in,
                              void* d_out, int out_size) {
    const float* x_raw = (const float*)d_in[0];
    const float* A     = (const float*)d_in[1];
    const float* b     = (const float*)d_in[2];
    const float* W1    = (const float*)d_in[3];
    const float* b1v   = (const float*)d_in[4];
    const float* w2    = (const float*)d_in[5];
    float* out = (float*)d_out;
    int P = in_sizes[0] / 32;           // number of flattened problems
    int blocks = (P + 3) / 4;           // 4 problems (warps) per block
    fw_kernel<<<blocks, 128>>>(x_raw, A, b, W1, b1v, w2, out, P);
}

// round 3
// speedup vs baseline: 1.3806x; 1.3806x over previous
#include <cuda_runtime.h>
#include <cuda_bf16.h>
#include <math.h>

namespace {

constexpr int NVc = 32;   // x dim
constexpr int MCc = 24;   // constraint rows in A
constexpr int MHc = 20;   // hard rows
constexpr int ITc = 200;  // ADMM iterations

// per-warp shared layout (floats)
constexpr int OFF_A = 0;            // A: 24 rows, stride 36
constexpr int OFF_M = 864;          // M workspace: 36 x 36
constexpr int OFF_T = 2160;         // t buffer (32)
constexpr int OFF_R = 2192;         // rhs (40)
constexpr int OFF_U = 2232;         // u (40)
constexpr int WARPF = 2304;         // 9216 bytes per warp

__device__ __forceinline__ float d4(float4 a, float4 b) {
    return a.x * b.x + a.y * b.y + a.z * b.z + a.w * b.w;
}

// In-place warp-parallel Gauss-Jordan inverse of SPD n x n, row stride 36.
template <int n>
__device__ __forceinline__ void gj_inv(float* Mw, int tid) {
#pragma unroll 1
    for (int k = 0; k < n; k++) {
        float piv = 1.0f / Mw[k * 36 + k];
        __syncwarp();
#pragma unroll 1
        for (int j = tid; j < n; j += 32)
            Mw[k * 36 + j] = (j == k) ? piv : Mw[k * 36 + j] * piv;
        __syncwarp();
#pragma unroll 1
        for (int i = tid; i < n; i += 32) {
            if (i == k) continue;
            float f = Mw[i * 36 + k];
            const float4* rk = reinterpret_cast<const float4*>(Mw + k * 36);
            float4*       ri = reinterpret_cast<float4*>(Mw + i * 36);
#pragma unroll
            for (int q = 0; q < n / 4; q++) {
                float4 a = ri[q];
                float4 bq = rk[q];
                a.x = fmaf(-f, bq.x, a.x);
                a.y = fmaf(-f, bq.y, a.y);
                a.z = fmaf(-f, bq.z, a.z);
                a.w = fmaf(-f, bq.w, a.w);
                ri[q] = a;
            }
            Mw[i * 36 + k] = -f * piv;
        }
        __syncwarp();
    }
}

__global__ void __launch_bounds__(128, 4)
fw_kernel(const float* __restrict__ x_raw, const float* __restrict__ Ain,
          const float* __restrict__ bin, const float* __restrict__ W1,
          const float* __restrict__ b1v, const float* __restrict__ w2,
          float* __restrict__ out, int P)
{
    __shared__ __align__(16) float smem_all[4 * WARPF];
    const int tid = threadIdx.x & 31;
    const int wid = threadIdx.x >> 5;
    const int p = blockIdx.x * 4 + wid;
    if (p >= P) return;
    float* sw = smem_all + wid * WARPF;

    // ------------------------------------------------------------------
    // Load A (smem rows + register column), b, x_raw
    // ------------------------------------------------------------------
    float Acol[MCc];
    {
        const float* Ap = Ain + (size_t)p * (MCc * NVc);
#pragma unroll
        for (int r = 0; r < MCc; r++) {
            float v = Ap[r * NVc + tid];
            sw[OFF_A + r * 36 + tid] = v;
            Acol[r] = v;
        }
    }
    const float b_own = (tid < MCc) ? bin[(size_t)p * MCc + tid] : 0.0f;
    const float xr = x_raw[(size_t)p * NVc + tid];
    __syncwarp();

    // Own A row in registers (lanes < 24); zeros elsewhere.
    // Lanes 28..31 will later be repurposed to hold Minv rows 32..35.
    float Arow[32];
    float m2tail[4];
#pragma unroll
    for (int j = 0; j < 32; j++) Arow[j] = 0.0f;
#pragma unroll
    for (int k = 0; k < 4; k++) m2tail[k] = 0.0f;
    if (tid < MCc) {
        const float4* ar = reinterpret_cast<const float4*>(sw + OFF_A + tid * 36);
#pragma unroll
        for (int q = 0; q < 8; q++) {
            float4 v = ar[q];
            Arow[4 * q] = v.x; Arow[4 * q + 1] = v.y; Arow[4 * q + 2] = v.z; Arow[4 * q + 3] = v.w;
        }
    }

    // ------------------------------------------------------------------
    // Anchor M = [[A^T A + 2I, -A_soft^T], [-A_soft, 4I]]  (36x36)
    // ------------------------------------------------------------------
    {
        float mr[36];
#pragma unroll
        for (int e = 0; e < 36; e++) mr[e] = 0.0f;
#pragma unroll
        for (int r = 0; r < MCc; r++) {
            const float4* ar = reinterpret_cast<const float4*>(sw + OFF_A + r * 36);
            float a = Acol[r];
#pragma unroll
            for (int q = 0; q < 8; q++) {
                float4 v = ar[q];
                mr[4 * q + 0] = fmaf(a, v.x, mr[4 * q + 0]);
                mr[4 * q + 1] = fmaf(a, v.y, mr[4 * q + 1]);
                mr[4 * q + 2] = fmaf(a, v.z, mr[4 * q + 2]);
                mr[4 * q + 3] = fmaf(a, v.w, mr[4 * q + 3]);
            }
        }
#pragma unroll
        for (int k = 0; k < 4; k++) mr[32 + k] = -Acol[MHc + k];
        float4* md = reinterpret_cast<float4*>(sw + OFF_M + tid * 36);
#pragma unroll
        for (int q = 0; q < 9; q++)
            md[q] = make_float4(mr[4 * q], mr[4 * q + 1], mr[4 * q + 2], mr[4 * q + 3]);
        sw[OFF_M + tid * 36 + tid] += 2.0f;
    }
    __syncwarp();
    if (tid < 4) {  // slack rows 32..35
        float* md = sw + OFF_M + (32 + tid) * 36;
        const float* as = sw + OFF_A + (MHc + tid) * 36;
#pragma unroll
        for (int e = 0; e < 32; e++) md[e] = -as[e];
#pragma unroll
        for (int j = 0; j < 4; j++) md[32 + j] = (j == tid) ? 4.0f : 0.0f;
    }
    __syncwarp();

    gj_inv<36>(sw + OFF_M, tid);

    float minv[36];
    {
        const float4* ms = reinterpret_cast<const float4*>(sw + OFF_M + tid * 36);
#pragma unroll
        for (int q = 0; q < 9; q++) {
            float4 v = ms[q];
            minv[4 * q] = v.x; minv[4 * q + 1] = v.y; minv[4 * q + 2] = v.z; minv[4 * q + 3] = v.w;
        }
    }
    // lanes 28..31: hold Minv row 32+(tid-28) in the (otherwise zero) Arow regs
    if (tid >= 28) {
        const float4* ms = reinterpret_cast<const float4*>(sw + OFF_M + (tid + 4) * 36);
#pragma unroll
        for (int q = 0; q < 8; q++) {
            float4 v = ms[q];
            Arow[4 * q] = v.x; Arow[4 * q + 1] = v.y; Arow[4 * q + 2] = v.z; Arow[4 * q + 3] = v.w;
        }
        float4 v = ms[8];
        m2tail[0] = v.x; m2tail[1] = v.y; m2tail[2] = v.z; m2tail[3] = v.w;
    }

    // ------------------------------------------------------------------
    // Anchor ADMM. Rows 0..27 -> lanes 0..27 (y1,t1); rows 28..59 (-I_n)
    // -> lane tid (y3,t3). t = rho*z - y = z - y here.
    // ------------------------------------------------------------------
    float y1 = 0.0f, t1 = 0.0f, y3 = 0.0f, t3 = 0.0f, u_own = 0.0f;
    const float h1 = (tid < MCc) ? b_own : 0.0f;
    if (tid < 28) sw[OFF_T + tid] = 0.0f;
#pragma unroll 1
    for (int it = 0; it <= ITc; ++it) {
        __syncwarp();
        // rhs_x[tid] = xr + sum_r A[r][tid] t[r] - t3;  rhs_s[k] = -t[20+k]-t[24+k]
        {
            const float4* t4 = reinterpret_cast<const float4*>(sw + OFF_T);
            float a0 = xr, a1 = 0.0f;
#pragma unroll
            for (int q = 0; q < 6; q++) {
                float4 tv = t4[q];
                float s = Acol[4 * q] * tv.x + Acol[4 * q + 1] * tv.y
                        + Acol[4 * q + 2] * tv.z + Acol[4 * q + 3] * tv.w;
                if (q & 1) a1 += s; else a0 += s;
            }
            sw[OFF_R + tid] = a0 + a1 - t3;
            if (tid >= 28) {
                int k = tid - 28;
                sw[OFF_R + 32 + k] = -sw[OFF_T + MHc + k] - sw[OFF_T + MCc + k];
            }
        }
        __syncwarp();
        // u = Minv rhs. Row tid from minv regs; rows 32..35 from lanes 28..31's
        // Arow/m2tail registers (register-resident, no smem reads).
        {
            const float4* r4 = reinterpret_cast<const float4*>(sw + OFF_R);
            float a0 = 0.0f, a1 = 0.0f, bx0 = 0.0f, bx1 = 0.0f;
#pragma unroll
            for (int q = 0; q < 8; q++) {
                float4 rv = r4[q];
                float s = minv[4 * q] * rv.x + minv[4 * q + 1] * rv.y
                        + minv[4 * q + 2] * rv.z + minv[4 * q + 3] * rv.w;
                float sb = Arow[4 * q] * rv.x + Arow[4 * q + 1] * rv.y
                         + Arow[4 * q + 2] * rv.z + Arow[4 * q + 3] * rv.w;
                if (q & 1) { a1 += s; bx1 += sb; } else { a0 += s; bx0 += sb; }
            }
            float4 rv = r4[8];
            a0 += minv[32] * rv.x + minv[33] * rv.y + minv[34] * rv.z + minv[35] * rv.w;
            bx0 += m2tail[0] * rv.x + m2tail[1] * rv.y + m2tail[2] * rv.z + m2tail[3] * rv.w;
            u_own = a0 + a1;
            sw[OFF_U + tid] = u_own;
            if (tid >= 28) sw[OFF_U + 32 + (tid - 28)] = bx0 + bx1;
        }
        __syncwarp();
        if (it == ITc) break;
        // Gu from register A rows + broadcast u, then z/y/t updates
        {
            const float4* u4 = reinterpret_cast<const float4*>(sw + OFF_U);
            float r0 = 0.0f, r1 = 0.0f;
#pragma unroll
            for (int q = 0; q < 8; q++) {
                float4 uv = u4[q];
                float s = Arow[4 * q] * uv.x + Arow[4 * q + 1] * uv.y
                        + Arow[4 * q + 2] * uv.z + Arow[4 * q + 3] * uv.w;
                if (q & 1) r1 += s; else r0 += s;
            }
            float rowdot = r0 + r1;
            float4 us = u4[8];  // u[32..35]
            float gu1;
            if (tid < MHc) {
                gu1 = rowdot;
            } else {
                int kk = (tid < MCc) ? (tid - MHc) : (tid - MCc);
                float usk = (kk == 0) ? us.x : (kk == 1) ? us.y : (kk == 2) ? us.z : us.w;
                gu1 = (tid < MCc) ? (rowdot - usk) : (-usk);
            }
            float w = gu1 + y1;
            float z = fminf(w, h1);
            y1 = w - z;
            t1 = z - y1;
            if (tid < 28) sw[OFF_T + tid] = t1;
            float w3 = y3 - u_own;   // Gu[28+tid] = -u[tid]
            float z3 = fminf(w3, 0.0f);
            y3 = w3 - z3;
            t3 = z3 - y3;
        }
    }
    const float xf_own = u_own;   // x_feas[tid]; full u also in sw[OFF_U]

    // ------------------------------------------------------------------
    // Gradient of critic: g = W1 @ (w2 * (1 - tanh^2(x W1 + b1)))
    // ------------------------------------------------------------------
    float g_own;
    {
        float vh[8];
#pragma unroll
        for (int hb = 0; hb < 8; ++hb) {
            int h = hb * 32 + tid;
            float z0 = b1v[h], z1b = 0.0f;
            const float4* x4 = reinterpret_cast<const float4*>(sw + OFF_U);
#pragma unroll
            for (int q = 0; q < 8; q++) {
                float4 xv = x4[q];
                float s = xv.x * W1[(4 * q + 0) * 256 + h] + xv.y * W1[(4 * q + 1) * 256 + h]
                        + xv.z * W1[(4 * q + 2) * 256 + h] + xv.w * W1[(4 * q + 3) * 256 + h];
                if (q & 1) z1b += s; else z0 += s;
            }
            float th = tanhf(z0 + z1b);
            vh[hb] = w2[h] * (1.0f - th * th);
        }
        __syncwarp();
        // partial g per lane in two 16-wide passes (register pressure), via
        // the now-free M workspace for the transpose-reduce
#pragma unroll 1
        for (int half = 0; half < 2; ++half) {
            float gp[16];
#pragma unroll
            for (int j = 0; j < 16; j++) gp[j] = 0.0f;
#pragma unroll
            for (int hb = 0; hb < 8; ++hb) {
                int h = hb * 32 + tid;
                float v = vh[hb];
#pragma unroll
                for (int j = 0; j < 16; j++)
                    gp[j] = fmaf(W1[(half * 16 + j) * 256 + h], v, gp[j]);
            }
            float4* md = reinterpret_cast<float4*>(sw + OFF_M + tid * 36) + half * 4;
#pragma unroll
            for (int q = 0; q < 4; q++)
                md[q] = make_float4(gp[4 * q], gp[4 * q + 1], gp[4 * q + 2], gp[4 * q + 3]);
        }
        __syncwarp();
        float gs0 = 0.0f, gs1 = 0.0f;
#pragma unroll
        for (int i = 0; i < 32; i++) {
            float v = sw[OFF_M + i * 36 + tid];
            if (i & 1) gs1 += v; else gs0 += v;
        }
        g_own = gs0 + gs1;
    }
    __syncwarp();

    // lanes 28..31: restore Arow to zeros for the LMO loop
    if (tid >= 28) {
#pragma unroll
        for (int j = 0; j < 32; j++) Arow[j] = 0.0f;
    }

    // ------------------------------------------------------------------
    // LMO M = A^T A + I  (32x32)
    // ------------------------------------------------------------------
    {
        float mr[32];
#pragma unroll
        for (int e = 0; e < 32; e++) mr[e] = 0.0f;
#pragma unroll
        for (int r = 0; r < MCc; r++) {
            const float4* ar = reinterpret_cast<const float4*>(sw + OFF_A + r * 36);
            float a = Acol[r];
#pragma unroll
            for (int q = 0; q < 8; q++) {
                float4 v = ar[q];
                mr[4 * q + 0] = fmaf(a, v.x, mr[4 * q + 0]);
                mr[4 * q + 1] = fmaf(a, v.y, mr[4 * q + 1]);
                mr[4 * q + 2] = fmaf(a, v.z, mr[4 * q + 2]);
                mr[4 * q + 3] = fmaf(a, v.w, mr[4 * q + 3]);
            }
        }
        float4* md = reinterpret_cast<float4*>(sw + OFF_M + tid * 36);
#pragma unroll
        for (int q = 0; q < 8; q++)
            md[q] = make_float4(mr[4 * q], mr[4 * q + 1], mr[4 * q + 2], mr[4 * q + 3]);
        sw[OFF_M + tid * 36 + tid] += 1.0f;
    }
    __syncwarp();

    gj_inv<32>(sw + OFF_M, tid);
    {
        const float4* ms = reinterpret_cast<const float4*>(sw + OFF_M + tid * 36);
#pragma unroll
        for (int q = 0; q < 8; q++) {
            float4 v = ms[q];
            minv[4 * q] = v.x; minv[4 * q + 1] = v.y; minv[4 * q + 2] = v.z; minv[4 * q + 3] = v.w;
        }
    }

    // ------------------------------------------------------------------
    // LMO ADMM: rows 0..23 (A, h=b) on lanes 0..23; rows 24..55 (-I, h=0)
    // ------------------------------------------------------------------
    y1 = 0.0f; t1 = 0.0f; y3 = 0.0f; t3 = 0.0f;
    sw[OFF_T + tid] = 0.0f;
#pragma unroll 1
    for (int it = 0; it <= ITc; ++it) {
        __syncwarp();
        {
            const float4* t4 = reinterpret_cast<const float4*>(sw + OFF_T);
            float a0 = g_own, a1 = 0.0f;
#pragma unroll
            for (int q = 0; q < 6; q++) {
                float4 tv = t4[q];
                float s = Acol[4 * q] * tv.x + Acol[4 * q + 1] * tv.y
                        + Acol[4 * q + 2] * tv.z + Acol[4 * q + 3] * tv.w;
                if (q & 1) a1 += s; else a0 += s;
            }
            sw[OFF_R + tid] = a0 + a1 - t3;
        }
        __syncwarp();
        {
            const float4* r4 = reinterpret_cast<const float4*>(sw + OFF_R);
            float a0 = 0.0f, a1 = 0.0f;
#pragma unroll
            for (int q = 0; q < 8; q++) {
                float4 rv = r4[q];
                float s = minv[4 * q] * rv.x + minv[4 * q + 1] * rv.y
                        + minv[4 * q + 2] * rv.z + minv[4 * q + 3] * rv.w;
                if (q & 1) a1 += s; else a0 += s;
            }
            u_own = a0 + a1;
            sw[OFF_U + tid] = u_own;
        }
        __syncwarp();
        if (it == ITc) break;
        {
            const float4* u4 = reinterpret_cast<const float4*>(sw + OFF_U);
            float r0 = 0.0f, r1 = 0.0f;
#pragma unroll
            for (int q = 0; q < 8; q++) {
                float4 uv = u4[q];
                float s = Arow[4 * q] * uv.x + Arow[4 * q + 1] * uv.y
                        + Arow[4 * q + 2] * uv.z + Arow[4 * q + 3] * uv.w;
                if (q & 1) r1 += s; else r0 += s;
            }
            float w = r0 + r1 + y1;
            float z = fminf(w, b_own);
            y1 = w - z;
            t1 = z - y1;
            if (tid < MCc) sw[OFF_T + tid] = t1;
            float w3 = y3 - u_own;   // Gu[24+tid] = -u[tid]
            float z3 = fminf(w3, 0.0f);
            y3 = w3 - z3;
            t3 = z3 - y3;
        }
    }

    // Frank-Wolfe blend
    out[(size_t)p * NVc + tid] = 0.9f * xf_own + 0.1f * u_own;
}

}  // namespace

extern "C" void kernel_launch(void* const* d_in, const int* in_sizes, int n_in,
                              void* d_out, int out_size) {
    const float* x_raw = (const float*)d_in[0];
    const float* A     = (const float*)d_in[1];
    const float* b     = (const float*)d_in[2];
    const float* W1    = (const float*)d_in[3];
    const float* b1v   = (const float*)d_in[4];
    const float* w2    = (const float*)d_in[5];
    float* out = (float*)d_out;
    int P = in_sizes[0] / 32;           // number of flattened problems
    int blocks = (P + 3) / 4;           // 4 problems (warps) per block
    fw_kernel<<<blocks, 128>>>(x_raw, A, b, W1, b1v, w2, out, P);
}

// round 4
// speedup vs baseline: 1.5899x; 1.1516x over previous
#include <cuda_runtime.h>
#include <cuda_bf16.h>
#include <math.h>

namespace {

constexpr int NVc = 32;   // x dim
constexpr int MCc = 24;   // constraint rows in A
constexpr int MHc = 20;   // hard rows
constexpr int ITc = 200;  // ADMM iterations

// per-warp shared layout (floats)
constexpr int OFF_A = 0;            // A: 24 rows, stride 36
constexpr int OFF_M = 864;          // M workspace: 36 x 36
constexpr int OFF_T = 2160;         // t1 buffer (28)
constexpr int OFF_R = 2192;         // rhs (36, pad 40)
constexpr int OFF_U = 2232;         // x_feas for gradient (32, pad 40)
constexpr int WARPF = 2304;         // 9216 bytes per warp

// In-place warp-parallel Gauss-Jordan inverse of SPD n x n, row stride 36.
// Pivot row cached in registers (read once per k).
template <int n>
__device__ __forceinline__ void gj_inv(float* Mw, int tid) {
#pragma unroll 1
    for (int k = 0; k < n; k++) {
        __syncwarp();
        float piv = 1.0f / Mw[k * 36 + k];
        float rk[n];
        const float4* rk4 = reinterpret_cast<const float4*>(Mw + k * 36);
#pragma unroll
        for (int q = 0; q < n / 4; q++) {
            float4 v = rk4[q];
            rk[4 * q] = v.x; rk[4 * q + 1] = v.y; rk[4 * q + 2] = v.z; rk[4 * q + 3] = v.w;
        }
        __syncwarp();
#pragma unroll 1
        for (int i = tid; i < n; i += 32) {
            float* ri = Mw + i * 36;
            if (i == k) {
#pragma unroll
                for (int j = 0; j < n; j++) ri[j] = rk[j] * piv;
                ri[k] = piv;
            } else {
                float f = ri[k] * piv;   // = M[i][k] / M[k][k]
                float4* r4 = reinterpret_cast<float4*>(ri);
#pragma unroll
                for (int q = 0; q < n / 4; q++) {
                    float4 a = r4[q];
                    a.x = fmaf(-f, rk[4 * q],     a.x);
                    a.y = fmaf(-f, rk[4 * q + 1], a.y);
                    a.z = fmaf(-f, rk[4 * q + 2], a.z);
                    a.w = fmaf(-f, rk[4 * q + 3], a.w);
                    r4[q] = a;
                }
                ri[k] = -f;
            }
        }
    }
    __syncwarp();
}

__global__ void __launch_bounds__(128, 4)
fw_kernel(const float* __restrict__ x_raw, const float* __restrict__ Ain,
          const float* __restrict__ bin, const float* __restrict__ W1,
          const float* __restrict__ b1v, const float* __restrict__ w2,
          float* __restrict__ out, int P)
{
    __shared__ __align__(16) float smem_all[4 * WARPF];
    const int tid = threadIdx.x & 31;
    const int wid = threadIdx.x >> 5;
    const int p = blockIdx.x * 4 + wid;
    if (p >= P) return;
    float* sw = smem_all + wid * WARPF;

    // ------------------------------------------------------------------
    // Load A (smem rows + register column), b, x_raw
    // ------------------------------------------------------------------
    float Acol[MCc];
    {
        const float* Ap = Ain + (size_t)p * (MCc * NVc);
#pragma unroll
        for (int r = 0; r < MCc; r++) {
            float v = Ap[r * NVc + tid];
            sw[OFF_A + r * 36 + tid] = v;
            Acol[r] = v;
        }
    }
    const float b_own = (tid < MCc) ? bin[(size_t)p * MCc + tid] : 0.0f;
    const float xr = x_raw[(size_t)p * NVc + tid];
    __syncwarp();

    float minv[36];   // lane's Minv row (anchor: 36; LMO: first 32)
    float GM[36];     // lane's (G*Minv) row  (anchor rows 0..27; LMO rows 0..23)
    float xf_own, u_own, g_own;

    // ==================================================================
    // ANCHOR QP
    // ==================================================================
    {
        // M = [[A^T A + 2I, -A_soft^T], [-A_soft, 4I]]  (36x36)
        {
            float mr[36];
#pragma unroll
            for (int e = 0; e < 36; e++) mr[e] = 0.0f;
#pragma unroll
            for (int r = 0; r < MCc; r++) {
                const float4* ar = reinterpret_cast<const float4*>(sw + OFF_A + r * 36);
                float a = Acol[r];
#pragma unroll
                for (int q = 0; q < 8; q++) {
                    float4 v = ar[q];
                    mr[4 * q + 0] = fmaf(a, v.x, mr[4 * q + 0]);
                    mr[4 * q + 1] = fmaf(a, v.y, mr[4 * q + 1]);
                    mr[4 * q + 2] = fmaf(a, v.z, mr[4 * q + 2]);
                    mr[4 * q + 3] = fmaf(a, v.w, mr[4 * q + 3]);
                }
            }
#pragma unroll
            for (int k = 0; k < 4; k++) mr[32 + k] = -Acol[MHc + k];
            float4* md = reinterpret_cast<float4*>(sw + OFF_M + tid * 36);
#pragma unroll
            for (int q = 0; q < 9; q++)
                md[q] = make_float4(mr[4 * q], mr[4 * q + 1], mr[4 * q + 2], mr[4 * q + 3]);
            sw[OFF_M + tid * 36 + tid] += 2.0f;
        }
        __syncwarp();
        if (tid < 4) {  // slack rows 32..35
            float* md = sw + OFF_M + (32 + tid) * 36;
            const float* as = sw + OFF_A + (MHc + tid) * 36;
#pragma unroll
            for (int e = 0; e < 32; e++) md[e] = -as[e];
#pragma unroll
            for (int j = 0; j < 4; j++) md[32 + j] = (j == tid) ? 4.0f : 0.0f;
        }
        __syncwarp();

        gj_inv<36>(sw + OFF_M, tid);

        // GM row for lane tid (rows 0..27 of G*Minv):
        //   rows 0..23:  A_r * Minv   (A_r = own A row)
        //   rows 20..23: additionally  - Minv[32+(r-20), :]
        //   rows 24..27: - Minv[32+(r-24), :]
#pragma unroll
        for (int e = 0; e < 36; e++) GM[e] = 0.0f;
#pragma unroll 1
        for (int jb = 0; jb < 8; jb++) {
            float4 av = make_float4(0.f, 0.f, 0.f, 0.f);
            if (tid < MCc)
                av = reinterpret_cast<const float4*>(sw + OFF_A + tid * 36)[jb];
#pragma unroll
            for (int c = 0; c < 4; c++) {
                int j = 4 * jb + c;
                float a = (c == 0) ? av.x : (c == 1) ? av.y : (c == 2) ? av.z : av.w;
                const float4* mrw = reinterpret_cast<const float4*>(sw + OFF_M + j * 36);
#pragma unroll
                for (int q = 0; q < 9; q++) {
                    float4 v = mrw[q];
                    GM[4 * q + 0] = fmaf(a, v.x, GM[4 * q + 0]);
                    GM[4 * q + 1] = fmaf(a, v.y, GM[4 * q + 1]);
                    GM[4 * q + 2] = fmaf(a, v.z, GM[4 * q + 2]);
                    GM[4 * q + 3] = fmaf(a, v.w, GM[4 * q + 3]);
                }
            }
        }
#pragma unroll
        for (int k2 = 0; k2 < 4; k2++) {   // slack-column corrections
            const float4* mrw = reinterpret_cast<const float4*>(sw + OFF_M + (32 + k2) * 36);
            if (tid == MHc + k2 || tid == MCc + k2) {
#pragma unroll
                for (int q = 0; q < 9; q++) {
                    float4 v = mrw[q];
                    GM[4 * q + 0] -= v.x; GM[4 * q + 1] -= v.y;
                    GM[4 * q + 2] -= v.z; GM[4 * q + 3] -= v.w;
                }
            }
        }
        // own Minv row
        {
            const float4* ms = reinterpret_cast<const float4*>(sw + OFF_M + tid * 36);
#pragma unroll
            for (int q = 0; q < 9; q++) {
                float4 v = ms[q];
                minv[4 * q] = v.x; minv[4 * q + 1] = v.y; minv[4 * q + 2] = v.z; minv[4 * q + 3] = v.w;
            }
        }

        // ADMM loop. Rows 0..27 (y1,t1) on lanes 0..27; rows 28..59 (-I_n) per-lane (y3,t3).
        float y1 = 0.0f, t1o = 0.0f, y3 = 0.0f, t3o = 0.0f;
        u_own = 0.0f;
        const float h1 = (tid < MCc) ? b_own : 0.0f;
        if (tid < 28) sw[OFF_T + tid] = 0.0f;
#pragma unroll 1
        for (int it = 0; it <= ITc; ++it) {
            __syncwarp();
            // rhs_x[tid] = xr + sum_r A[r][tid] t1[r] - t3_own ; rhs_s[k] = -t1[20+k]-t1[24+k]
            float4 tv0, tv1, tv2, tv3, tv4, tv5, tv6;
            {
                const float4* t4 = reinterpret_cast<const float4*>(sw + OFF_T);
                tv0 = t4[0]; tv1 = t4[1]; tv2 = t4[2];
                tv3 = t4[3]; tv4 = t4[4]; tv5 = t4[5]; tv6 = t4[6];
                float a0 = xr, a1 = 0.0f;
                a0 += Acol[0]  * tv0.x + Acol[1]  * tv0.y + Acol[2]  * tv0.z + Acol[3]  * tv0.w;
                a1 += Acol[4]  * tv1.x + Acol[5]  * tv1.y + Acol[6]  * tv1.z + Acol[7]  * tv1.w;
                a0 += Acol[8]  * tv2.x + Acol[9]  * tv2.y + Acol[10] * tv2.z + Acol[11] * tv2.w;
                a1 += Acol[12] * tv3.x + Acol[13] * tv3.y + Acol[14] * tv3.z + Acol[15] * tv3.w;
                a0 += Acol[16] * tv4.x + Acol[17] * tv4.y + Acol[18] * tv4.z + Acol[19] * tv4.w;
                a1 += Acol[20] * tv5.x + Acol[21] * tv5.y + Acol[22] * tv5.z + Acol[23] * tv5.w;
                sw[OFF_R + tid] = a0 + a1 - t3o;
                if (tid >= 28) {
                    int k = tid - 28;
                    float ta = (k == 0) ? tv5.x : (k == 1) ? tv5.y : (k == 2) ? tv5.z : tv5.w;
                    float tb = (k == 0) ? tv6.x : (k == 1) ? tv6.y : (k == 2) ? tv6.z : tv6.w;
                    sw[OFF_R + 32 + k] = -ta - tb;
                }
            }
            __syncwarp();
            // dual dot from one rhs broadcast: u_own = minv.rhs ; gu = GM.rhs
            float gu;
            {
                const float4* r4 = reinterpret_cast<const float4*>(sw + OFF_R);
                float a0 = 0.0f, a1 = 0.0f, g0 = 0.0f, g1 = 0.0f;
#pragma unroll
                for (int q = 0; q < 9; q++) {
                    float4 rv = r4[q];
                    float s = minv[4 * q] * rv.x + minv[4 * q + 1] * rv.y
                            + minv[4 * q + 2] * rv.z + minv[4 * q + 3] * rv.w;
                    float sg = GM[4 * q] * rv.x + GM[4 * q + 1] * rv.y
                             + GM[4 * q + 2] * rv.z + GM[4 * q + 3] * rv.w;
                    if (q & 1) { a1 += s; g1 += sg; } else { a0 += s; g0 += sg; }
                }
                u_own = a0 + a1;
                gu = g0 + g1;
            }
            if (it == ITc) break;
            // z/y/t updates
            float w = gu + y1;
            float z = fminf(w, h1);
            y1 = w - z;
            t1o = z - y1;
            if (tid < 28) sw[OFF_T + tid] = t1o;
            float w3 = y3 - u_own;   // Gu[28+tid] = -u[tid]
            float z3 = fminf(w3, 0.0f);
            y3 = w3 - z3;
            t3o = z3 - y3;
        }
        xf_own = u_own;
        sw[OFF_U + tid] = u_own;   // x_feas vector for the gradient phase
    }
    __syncwarp();

    // ==================================================================
    // Gradient of critic: g = W1 @ (w2 * (1 - tanh^2(x W1 + b1)))
    // ==================================================================
    {
        float vh[8];
#pragma unroll
        for (int hb = 0; hb < 8; ++hb) {
            int h = hb * 32 + tid;
            float z0 = b1v[h], z1b = 0.0f;
            const float4* x4 = reinterpret_cast<const float4*>(sw + OFF_U);
#pragma unroll
            for (int q = 0; q < 8; q++) {
                float4 xv = x4[q];
                float s = xv.x * W1[(4 * q + 0) * 256 + h] + xv.y * W1[(4 * q + 1) * 256 + h]
                        + xv.z * W1[(4 * q + 2) * 256 + h] + xv.w * W1[(4 * q + 3) * 256 + h];
                if (q & 1) z1b += s; else z0 += s;
            }
            float th = tanhf(z0 + z1b);
            vh[hb] = w2[h] * (1.0f - th * th);
        }
        __syncwarp();
        // partial g per lane in two 16-wide passes via the (free) M workspace
#pragma unroll 1
        for (int half = 0; half < 2; ++half) {
            float gp[16];
#pragma unroll
            for (int j = 0; j < 16; j++) gp[j] = 0.0f;
#pragma unroll
            for (int hb = 0; hb < 8; ++hb) {
                int h = hb * 32 + tid;
                float v = vh[hb];
#pragma unroll
                for (int j = 0; j < 16; j++)
                    gp[j] = fmaf(W1[(half * 16 + j) * 256 + h], v, gp[j]);
            }
            float4* md = reinterpret_cast<float4*>(sw + OFF_M + tid * 36) + half * 4;
#pragma unroll
            for (int q = 0; q < 4; q++)
                md[q] = make_float4(gp[4 * q], gp[4 * q + 1], gp[4 * q + 2], gp[4 * q + 3]);
        }
        __syncwarp();
        float gs0 = 0.0f, gs1 = 0.0f;
#pragma unroll
        for (int i = 0; i < 32; i++) {
            float v = sw[OFF_M + i * 36 + tid];
            if (i & 1) gs1 += v; else gs0 += v;
        }
        g_own = gs0 + gs1;
    }
    __syncwarp();

    // ==================================================================
    // LMO LP (same ADMM machinery, M = A^T A + I, 32x32)
    // ==================================================================
    {
        {
            float mr[32];
#pragma unroll
            for (int e = 0; e < 32; e++) mr[e] = 0.0f;
#pragma unroll
            for (int r = 0; r < MCc; r++) {
                const float4* ar = reinterpret_cast<const float4*>(sw + OFF_A + r * 36);
                float a = Acol[r];
#pragma unroll
                for (int q = 0; q < 8; q++) {
                    float4 v = ar[q];
                    mr[4 * q + 0] = fmaf(a, v.x, mr[4 * q + 0]);
                    mr[4 * q + 1] = fmaf(a, v.y, mr[4 * q + 1]);
                    mr[4 * q + 2] = fmaf(a, v.z, mr[4 * q + 2]);
                    mr[4 * q + 3] = fmaf(a, v.w, mr[4 * q + 3]);
                }
            }
            float4* md = reinterpret_cast<float4*>(sw + OFF_M + tid * 36);
#pragma unroll
            for (int q = 0; q < 8; q++)
                md[q] = make_float4(mr[4 * q], mr[4 * q + 1], mr[4 * q + 2], mr[4 * q + 3]);
            sw[OFF_M + tid * 36 + tid] += 1.0f;
        }
        __syncwarp();

        gj_inv<32>(sw + OFF_M, tid);

        // GM row = A_r * Minv (lanes 0..23); zeros elsewhere
#pragma unroll
        for (int e = 0; e < 32; e++) GM[e] = 0.0f;
#pragma unroll 1
        for (int jb = 0; jb < 8; jb++) {
            float4 av = make_float4(0.f, 0.f, 0.f, 0.f);
            if (tid < MCc)
                av = reinterpret_cast<const float4*>(sw + OFF_A + tid * 36)[jb];
#pragma unroll
            for (int c = 0; c < 4; c++) {
                int j = 4 * jb + c;
                float a = (c == 0) ? av.x : (c == 1) ? av.y : (c == 2) ? av.z : av.w;
                const float4* mrw = reinterpret_cast<const float4*>(sw + OFF_M + j * 36);
#pragma unroll
                for (int q = 0; q < 8; q++) {
                    float4 v = mrw[q];
                    GM[4 * q + 0] = fmaf(a, v.x, GM[4 * q + 0]);
                    GM[4 * q + 1] = fmaf(a, v.y, GM[4 * q + 1]);
                    GM[4 * q + 2] = fmaf(a, v.z, GM[4 * q + 2]);
                    GM[4 * q + 3] = fmaf(a, v.w, GM[4 * q + 3]);
                }
            }
        }
        {
            const float4* ms = reinterpret_cast<const float4*>(sw + OFF_M + tid * 36);
#pragma unroll
            for (int q = 0; q < 8; q++) {
                float4 v = ms[q];
                minv[4 * q] = v.x; minv[4 * q + 1] = v.y; minv[4 * q + 2] = v.z; minv[4 * q + 3] = v.w;
            }
        }

        // ADMM: rows 0..23 (A, h=b) on lanes 0..23; rows 24..55 (-I, h=0) per-lane
        float y1 = 0.0f, t1o = 0.0f, y3 = 0.0f, t3o = 0.0f;
        u_own = 0.0f;
        if (tid < MCc) sw[OFF_T + tid] = 0.0f;
#pragma unroll 1
        for (int it = 0; it <= ITc; ++it) {
            __syncwarp();
            {
                const float4* t4 = reinterpret_cast<const float4*>(sw + OFF_T);
                float4 tv0 = t4[0], tv1 = t4[1], tv2 = t4[2], tv3 = t4[3], tv4 = t4[4], tv5 = t4[5];
                float a0 = g_own, a1 = 0.0f;
                a0 += Acol[0]  * tv0.x + Acol[1]  * tv0.y + Acol[2]  * tv0.z + Acol[3]  * tv0.w;
                a1 += Acol[4]  * tv1.x + Acol[5]  * tv1.y + Acol[6]  * tv1.z + Acol[7]  * tv1.w;
                a0 += Acol[8]  * tv2.x + Acol[9]  * tv2.y + Acol[10] * tv2.z + Acol[11] * tv2.w;
                a1 += Acol[12] * tv3.x + Acol[13] * tv3.y + Acol[14] * tv3.z + Acol[15] * tv3.w;
                a0 += Acol[16] * tv4.x + Acol[17] * tv4.y + Acol[18] * tv4.z + Acol[19] * tv4.w;
                a1 += Acol[20] * tv5.x + Acol[21] * tv5.y + Acol[22] * tv5.z + Acol[23] * tv5.w;
                sw[OFF_R + tid] = a0 + a1 - t3o;
            }
            __syncwarp();
            float gu;
            {
                const float4* r4 = reinterpret_cast<const float4*>(sw + OFF_R);
                float a0 = 0.0f, a1 = 0.0f, g0 = 0.0f, g1 = 0.0f;
#pragma unroll
                for (int q = 0; q < 8; q++) {
                    float4 rv = r4[q];
                    float s = minv[4 * q] * rv.x + minv[4 * q + 1] * rv.y
                            + minv[4 * q + 2] * rv.z + minv[4 * q + 3] * rv.w;
                    float sg = GM[4 * q] * rv.x + GM[4 * q + 1] * rv.y
                             + GM[4 * q + 2] * rv.z + GM[4 * q + 3] * rv.w;
                    if (q & 1) { a1 += s; g1 += sg; } else { a0 += s; g0 += sg; }
                }
                u_own = a0 + a1;
                gu = g0 + g1;
            }
            if (it == ITc) break;
            float w = gu + y1;
            float z = fminf(w, b_own);
            y1 = w - z;
            t1o = z - y1;
            if (tid < MCc) sw[OFF_T + tid] = t1o;
            float w3 = y3 - u_own;   // Gu[24+tid] = -u[tid]
            float z3 = fminf(w3, 0.0f);
            y3 = w3 - z3;
            t3o = z3 - y3;
        }
    }

    // Frank-Wolfe blend
    out[(size_t)p * NVc + tid] = 0.9f * xf_own + 0.1f * u_own;
}

}  // namespace

extern "C" void kernel_launch(void* const* d_in, const int* in_sizes, int n_in,
                              void* d_out, int out_size) {
    const float* x_raw = (const float*)d_in[0];
    const float* A     = (const float*)d_in[1];
    const float* b     = (const float*)d_in[2];
    const float* W1    = (const float*)d_in[3];
    const float* b1v   = (const float*)d_in[4];
    const float* w2    = (const float*)d_in[5];
    float* out = (float*)d_out;
    int P = in_sizes[0] / 32;           // number of flattened problems
    int blocks = (P + 3) / 4;           // 4 problems (warps) per block
    fw_kernel<<<blocks, 128>>>(x_raw, A, b, W1, b1v, w2, out, P);
}

// round 6
// speedup vs baseline: 1.7849x; 1.1226x over previous
#include <cuda_runtime.h>
#include <cuda_bf16.h>
#include <math.h>

namespace {

constexpr int NVc = 32;   // x dim
constexpr int MCc = 24;   // constraint rows in A
constexpr int MHc = 20;   // hard rows
constexpr int ITc = 200;  // ADMM iterations (must match reference trajectory)

// per-warp shared layout (floats)
constexpr int OFF_A = 0;            // A: 24 rows, stride 36
constexpr int OFF_M = 864;          // M workspace: 32 x 36
constexpr int OFF_T = 2160;         // t1 buffer (28)
constexpr int OFF_R = 2192;         // rhs (32, pad 40)
constexpr int OFF_U = 2232;         // x_feas for gradient (32, pad 40)
constexpr int WARPF = 2304;         // 9216 bytes per warp

// In-place warp-parallel Gauss-Jordan inverse of SPD n x n, row stride 36.
// Pivot row cached in registers (read once per k).
template <int n>
__device__ __forceinline__ void gj_inv(float* Mw, int tid) {
#pragma unroll 1
    for (int k = 0; k < n; k++) {
        __syncwarp();
        float piv = 1.0f / Mw[k * 36 + k];
        float rk[n];
        const float4* rk4 = reinterpret_cast<const float4*>(Mw + k * 36);
#pragma unroll
        for (int q = 0; q < n / 4; q++) {
            float4 v = rk4[q];
            rk[4 * q] = v.x; rk[4 * q + 1] = v.y; rk[4 * q + 2] = v.z; rk[4 * q + 3] = v.w;
        }
        __syncwarp();
#pragma unroll 1
        for (int i = tid; i < n; i += 32) {
            float* ri = Mw + i * 36;
            if (i == k) {
#pragma unroll
                for (int j = 0; j < n; j++) ri[j] = rk[j] * piv;
                ri[k] = piv;
            } else {
                float f = ri[k] * piv;   // = M[i][k] / M[k][k]
                float4* r4 = reinterpret_cast<float4*>(ri);
#pragma unroll
                for (int q = 0; q < n / 4; q++) {
                    float4 a = r4[q];
                    a.x = fmaf(-f, rk[4 * q],     a.x);
                    a.y = fmaf(-f, rk[4 * q + 1], a.y);
                    a.z = fmaf(-f, rk[4 * q + 2], a.z);
                    a.w = fmaf(-f, rk[4 * q + 3], a.w);
                    r4[q] = a;
                }
                ri[k] = -f;
            }
        }
    }
    __syncwarp();
}

__global__ void __launch_bounds__(128, 4)
fw_kernel(const float* __restrict__ x_raw, const float* __restrict__ Ain,
          const float* __restrict__ bin, const float* __restrict__ W1,
          const float* __restrict__ b1v, const float* __restrict__ w2,
          float* __restrict__ out, int P)
{
    __shared__ __align__(16) float smem_all[4 * WARPF];
    const int tid = threadIdx.x & 31;
    const int wid = threadIdx.x >> 5;
    const int p = blockIdx.x * 4 + wid;
    if (p >= P) return;
    float* sw = smem_all + wid * WARPF;

    // ------------------------------------------------------------------
    // Load A (smem rows + register column), b, x_raw
    // ------------------------------------------------------------------
    float Acol[MCc];
    {
        const float* Ap = Ain + (size_t)p * (MCc * NVc);
#pragma unroll
        for (int r = 0; r < MCc; r++) {
            float v = Ap[r * NVc + tid];
            sw[OFF_A + r * 36 + tid] = v;
            Acol[r] = v;
        }
    }
    const float b_own = (tid < MCc) ? bin[(size_t)p * MCc + tid] : 0.0f;
    const float xr = x_raw[(size_t)p * NVc + tid];
    __syncwarp();

    float minv[32];   // lane's row of the 32x32 inverse
    float GM[32];     // lane's row of (G-effective * Kinv)
    float xf_own, u_own, g_own;

    // ==================================================================
    // ANCHOR QP via Schur complement on the 4 slack dims:
    //   Ks = A_h^T A_h + 0.75 A_s^T A_s + 2I   (32x32)
    //   r_eff = r1 + 0.25 A_s^T r2,   u_x = Ks^{-1} r_eff
    //   Gu rows: 0..19: A_r u_x ; 20+k: 0.75 A_{20+k} u_x - r2_k/4 ;
    //            24+k: -0.25 A_{20+k} u_x - r2_k/4 ; 28+j: -u_x[j]
    // ==================================================================
    {
        // Build Ks (row tid) via weighted rank-1 accumulation
        {
            float mr[32];
#pragma unroll
            for (int e = 0; e < 32; e++) mr[e] = 0.0f;
#pragma unroll
            for (int r = 0; r < MCc; r++) {
                const float4* ar = reinterpret_cast<const float4*>(sw + OFF_A + r * 36);
                float a = (r < MHc) ? Acol[r] : 0.75f * Acol[r];
#pragma unroll
                for (int q = 0; q < 8; q++) {
                    float4 v = ar[q];
                    mr[4 * q + 0] = fmaf(a, v.x, mr[4 * q + 0]);
                    mr[4 * q + 1] = fmaf(a, v.y, mr[4 * q + 1]);
                    mr[4 * q + 2] = fmaf(a, v.z, mr[4 * q + 2]);
                    mr[4 * q + 3] = fmaf(a, v.w, mr[4 * q + 3]);
                }
            }
            float4* md = reinterpret_cast<float4*>(sw + OFF_M + tid * 36);
#pragma unroll
            for (int q = 0; q < 8; q++)
                md[q] = make_float4(mr[4 * q], mr[4 * q + 1], mr[4 * q + 2], mr[4 * q + 3]);
            sw[OFF_M + tid * 36 + tid] += 2.0f;
        }
        __syncwarp();

        gj_inv<32>(sw + OFF_M, tid);

        // GM row: coef * (A_src * Kinv). src row: tid<24 -> tid; 24..27 -> tid-4.
        {
            const float coef = (tid < MHc) ? 1.0f : (tid < MCc) ? 0.75f : -0.25f;
            const int src = (tid < MCc) ? tid : tid - 4;
#pragma unroll
            for (int e = 0; e < 32; e++) GM[e] = 0.0f;
#pragma unroll 1
            for (int jb = 0; jb < 8; jb++) {
                float4 av = make_float4(0.f, 0.f, 0.f, 0.f);
                if (tid < 28)
                    av = reinterpret_cast<const float4*>(sw + OFF_A + src * 36)[jb];
                av.x *= coef; av.y *= coef; av.z *= coef; av.w *= coef;
#pragma unroll
                for (int c = 0; c < 4; c++) {
                    int j = 4 * jb + c;
                    float a = (c == 0) ? av.x : (c == 1) ? av.y : (c == 2) ? av.z : av.w;
                    const float4* mrw = reinterpret_cast<const float4*>(sw + OFF_M + j * 36);
#pragma unroll
                    for (int q = 0; q < 8; q++) {
                        float4 v = mrw[q];
                        GM[4 * q + 0] = fmaf(a, v.x, GM[4 * q + 0]);
                        GM[4 * q + 1] = fmaf(a, v.y, GM[4 * q + 1]);
                        GM[4 * q + 2] = fmaf(a, v.z, GM[4 * q + 2]);
                        GM[4 * q + 3] = fmaf(a, v.w, GM[4 * q + 3]);
                    }
                }
            }
        }
        // own Kinv row
        {
            const float4* ms = reinterpret_cast<const float4*>(sw + OFF_M + tid * 36);
#pragma unroll
            for (int q = 0; q < 8; q++) {
                float4 v = ms[q];
                minv[4 * q] = v.x; minv[4 * q + 1] = v.y; minv[4 * q + 2] = v.z; minv[4 * q + 3] = v.w;
            }
        }

        // ADMM loop. Rows 0..27 (y1,t1) on lanes 0..27; rows 28..59 (-I_n) per-lane (y3,t3).
        float y1 = 0.0f, t1o = 0.0f, y3 = 0.0f, t3o = 0.0f;
        u_own = 0.0f;
        const float h1 = (tid < MCc) ? b_own : 0.0f;
        if (tid < 28) sw[OFF_T + tid] = 0.0f;
        float r2_own = 0.0f;   // r2_k source for lanes 20..27
#pragma unroll 1
        for (int it = 0; it <= ITc; ++it) {
            __syncwarp();
            // r_eff[tid] = xr + sum_{r<24} A[r][tid] t1[r] + 0.25*sum_k A[20+k][tid]*r2_k - t3_own
            {
                const float4* t4 = reinterpret_cast<const float4*>(sw + OFF_T);
                float4 tv0 = t4[0], tv1 = t4[1], tv2 = t4[2], tv3 = t4[3],
                       tv4 = t4[4], tv5 = t4[5], tv6 = t4[6];
                float r2x = -tv5.x - tv6.x;   // r2_0
                float r2y = -tv5.y - tv6.y;
                float r2z = -tv5.z - tv6.z;
                float r2w = -tv5.w - tv6.w;
                int k = tid & 3;
                r2_own = (k == 0) ? r2x : (k == 1) ? r2y : (k == 2) ? r2z : r2w;
                float a0 = xr, a1 = 0.0f;
                a0 += Acol[0]  * tv0.x + Acol[1]  * tv0.y + Acol[2]  * tv0.z + Acol[3]  * tv0.w;
                a1 += Acol[4]  * tv1.x + Acol[5]  * tv1.y + Acol[6]  * tv1.z + Acol[7]  * tv1.w;
                a0 += Acol[8]  * tv2.x + Acol[9]  * tv2.y + Acol[10] * tv2.z + Acol[11] * tv2.w;
                a1 += Acol[12] * tv3.x + Acol[13] * tv3.y + Acol[14] * tv3.z + Acol[15] * tv3.w;
                a0 += Acol[16] * tv4.x + Acol[17] * tv4.y + Acol[18] * tv4.z + Acol[19] * tv4.w;
                a1 += Acol[20] * (tv5.x + 0.25f * r2x) + Acol[21] * (tv5.y + 0.25f * r2y)
                    + Acol[22] * (tv5.z + 0.25f * r2z) + Acol[23] * (tv5.w + 0.25f * r2w);
                sw[OFF_R + tid] = a0 + a1 - t3o;
            }
            __syncwarp();
            // dual dot from one r_eff broadcast: u_own = minv.r ; gu = GM.r (+slack term)
            float gu;
            {
                const float4* r4 = reinterpret_cast<const float4*>(sw + OFF_R);
                float a0 = 0.0f, a1 = 0.0f, g0 = 0.0f, g1 = 0.0f;
#pragma unroll
                for (int q = 0; q < 8; q++) {
                    float4 rv = r4[q];
                    float s = minv[4 * q] * rv.x + minv[4 * q + 1] * rv.y
                            + minv[4 * q + 2] * rv.z + minv[4 * q + 3] * rv.w;
                    float sg = GM[4 * q] * rv.x + GM[4 * q + 1] * rv.y
                             + GM[4 * q + 2] * rv.z + GM[4 * q + 3] * rv.w;
                    if (q & 1) { a1 += s; g1 += sg; } else { a0 += s; g0 += sg; }
                }
                u_own = a0 + a1;
                gu = g0 + g1;
                if (tid >= MHc) gu -= 0.25f * r2_own;   // rows 20..27 slack term
            }
            if (it == ITc) break;
            // z/y/t updates
            float w = gu + y1;
            float z = fminf(w, h1);
            y1 = w - z;
            t1o = z - y1;
            if (tid < 28) sw[OFF_T + tid] = t1o;
            float w3 = y3 - u_own;   // Gu[28+tid] = -u[tid]
            float z3 = fminf(w3, 0.0f);
            y3 = w3 - z3;
            t3o = z3 - y3;
        }
        xf_own = u_own;
        sw[OFF_U + tid] = u_own;   // x_feas vector for the gradient phase
    }
    __syncwarp();

    // ==================================================================
    // Gradient of critic: g = W1 @ (w2 * (1 - tanh^2(x W1 + b1)))
    // ==================================================================
    {
        float vh[8];
#pragma unroll
        for (int hb = 0; hb < 8; ++hb) {
            int h = hb * 32 + tid;
            float z0 = b1v[h], z1b = 0.0f;
            const float4* x4 = reinterpret_cast<const float4*>(sw + OFF_U);
#pragma unroll
            for (int q = 0; q < 8; q++) {
                float4 xv = x4[q];
                float s = xv.x * W1[(4 * q + 0) * 256 + h] + xv.y * W1[(4 * q + 1) * 256 + h]
                        + xv.z * W1[(4 * q + 2) * 256 + h] + xv.w * W1[(4 * q + 3) * 256 + h];
                if (q & 1) z1b += s; else z0 += s;
            }
            float th = tanhf(z0 + z1b);
            vh[hb] = w2[h] * (1.0f - th * th);
        }
        __syncwarp();
        // partial g per lane in two 16-wide passes via the (free) M workspace
#pragma unroll 1
        for (int half = 0; half < 2; ++half) {
            float gp[16];
#pragma unroll
            for (int j = 0; j < 16; j++) gp[j] = 0.0f;
#pragma unroll
            for (int hb = 0; hb < 8; ++hb) {
                int h = hb * 32 + tid;
                float v = vh[hb];
#pragma unroll
                for (int j = 0; j < 16; j++)
                    gp[j] = fmaf(W1[(half * 16 + j) * 256 + h], v, gp[j]);
            }
            float4* md = reinterpret_cast<float4*>(sw + OFF_M + tid * 36) + half * 4;
#pragma unroll
            for (int q = 0; q < 4; q++)
                md[q] = make_float4(gp[4 * q], gp[4 * q + 1], gp[4 * q + 2], gp[4 * q + 3]);
        }
        __syncwarp();
        float gs0 = 0.0f, gs1 = 0.0f;
#pragma unroll
        for (int i = 0; i < 32; i++) {
            float v = sw[OFF_M + i * 36 + tid];
            if (i & 1) gs1 += v; else gs0 += v;
        }
        g_own = gs0 + gs1;
    }
    __syncwarp();

    // ==================================================================
    // LMO LP (same ADMM machinery, M = A^T A + I, 32x32)
    // ==================================================================
    {
        {
            float mr[32];
#pragma unroll
            for (int e = 0; e < 32; e++) mr[e] = 0.0f;
#pragma unroll
            for (int r = 0; r < MCc; r++) {
                const float4* ar = reinterpret_cast<const float4*>(sw + OFF_A + r * 36);
                float a = Acol[r];
#pragma unroll
                for (int q = 0; q < 8; q++) {
                    float4 v = ar[q];
                    mr[4 * q + 0] = fmaf(a, v.x, mr[4 * q + 0]);
                    mr[4 * q + 1] = fmaf(a, v.y, mr[4 * q + 1]);
                    mr[4 * q + 2] = fmaf(a, v.z, mr[4 * q + 2]);
                    mr[4 * q + 3] = fmaf(a, v.w, mr[4 * q + 3]);
                }
            }
            float4* md = reinterpret_cast<float4*>(sw + OFF_M + tid * 36);
#pragma unroll
            for (int q = 0; q < 8; q++)
                md[q] = make_float4(mr[4 * q], mr[4 * q + 1], mr[4 * q + 2], mr[4 * q + 3]);
            sw[OFF_M + tid * 36 + tid] += 1.0f;
        }
        __syncwarp();

        gj_inv<32>(sw + OFF_M, tid);

        // GM row = A_r * Minv (lanes 0..23); zeros elsewhere
#pragma unroll
        for (int e = 0; e < 32; e++) GM[e] = 0.0f;
#pragma unroll 1
        for (int jb = 0; jb < 8; jb++) {
            float4 av = make_float4(0.f, 0.f, 0.f, 0.f);
            if (tid < MCc)
                av = reinterpret_cast<const float4*>(sw + OFF_A + tid * 36)[jb];
#pragma unroll
            for (int c = 0; c < 4; c++) {
                int j = 4 * jb + c;
                float a = (c == 0) ? av.x : (c == 1) ? av.y : (c == 2) ? av.z : av.w;
                const float4* mrw = reinterpret_cast<const float4*>(sw + OFF_M + j * 36);
#pragma unroll
                for (int q = 0; q < 8; q++) {
                    float4 v = mrw[q];
                    GM[4 * q + 0] = fmaf(a, v.x, GM[4 * q + 0]);
                    GM[4 * q + 1] = fmaf(a, v.y, GM[4 * q + 1]);
                    GM[4 * q + 2] = fmaf(a, v.z, GM[4 * q + 2]);
                    GM[4 * q + 3] = fmaf(a, v.w, GM[4 * q + 3]);
                }
            }
        }
        {
            const float4* ms = reinterpret_cast<const float4*>(sw + OFF_M + tid * 36);
#pragma unroll
            for (int q = 0; q < 8; q++) {
                float4 v = ms[q];
                minv[4 * q] = v.x; minv[4 * q + 1] = v.y; minv[4 * q + 2] = v.z; minv[4 * q + 3] = v.w;
            }
        }

        // ADMM: rows 0..23 (A, h=b) on lanes 0..23; rows 24..55 (-I, h=0) per-lane
        float y1 = 0.0f, t1o = 0.0f, y3 = 0.0f, t3o = 0.0f;
        u_own = 0.0f;
        if (tid < MCc) sw[OFF_T + tid] = 0.0f;
#pragma unroll 1
        for (int it = 0; it <= ITc; ++it) {
            __syncwarp();
            {
                const float4* t4 = reinterpret_cast<const float4*>(sw + OFF_T);
                float4 tv0 = t4[0], tv1 = t4[1], tv2 = t4[2], tv3 = t4[3], tv4 = t4[4], tv5 = t4[5];
                float a0 = g_own, a1 = 0.0f;
                a0 += Acol[0]  * tv0.x + Acol[1]  * tv0.y + Acol[2]  * tv0.z + Acol[3]  * tv0.w;
                a1 += Acol[4]  * tv1.x + Acol[5]  * tv1.y + Acol[6]  * tv1.z + Acol[7]  * tv1.w;
                a0 += Acol[8]  * tv2.x + Acol[9]  * tv2.y + Acol[10] * tv2.z + Acol[11] * tv2.w;
                a1 += Acol[12] * tv3.x + Acol[13] * tv3.y + Acol[14] * tv3.z + Acol[15] * tv3.w;
                a0 += Acol[16] * tv4.x + Acol[17] * tv4.y + Acol[18] * tv4.z + Acol[19] * tv4.w;
                a1 += Acol[20] * tv5.x + Acol[21] * tv5.y + Acol[22] * tv5.z + Acol[23] * tv5.w;
                sw[OFF_R + tid] = a0 + a1 - t3o;
            }
            __syncwarp();
            float gu;
            {
                const float4* r4 = reinterpret_cast<const float4*>(sw + OFF_R);
                float a0 = 0.0f, a1 = 0.0f, g0 = 0.0f, g1 = 0.0f;
#pragma unroll
                for (int q = 0; q < 8; q++) {
                    float4 rv = r4[q];
                    float s = minv[4 * q] * rv.x + minv[4 * q + 1] * rv.y
                            + minv[4 * q + 2] * rv.z + minv[4 * q + 3] * rv.w;
                    float sg = GM[4 * q] * rv.x + GM[4 * q + 1] * rv.y
                             + GM[4 * q + 2] * rv.z + GM[4 * q + 3] * rv.w;
                    if (q & 1) { a1 += s; g1 += sg; } else { a0 += s; g0 += sg; }
                }
                u_own = a0 + a1;
                gu = g0 + g1;
            }
            if (it == ITc) break;
            float w = gu + y1;
            float z = fminf(w, b_own);
            y1 = w - z;
            t1o = z - y1;
            if (tid < MCc) sw[OFF_T + tid] = t1o;
            float w3 = y3 - u_own;   // Gu[24+tid] = -u[tid]
            float z3 = fminf(w3, 0.0f);
            y3 = w3 - z3;
            t3o = z3 - y3;
        }
    }

    // Frank-Wolfe blend
    out[(size_t)p * NVc + tid] = 0.9f * xf_own + 0.1f * u_own;
}

}  // namespace

extern "C" void kernel_launch(void* const* d_in, const int* in_sizes, int n_in,
                              void* d_out, int out_size) {
    const float* x_raw = (const float*)d_in[0];
    const float* A     = (const float*)d_in[1];
    const float* b     = (const float*)d_in[2];
    const float* W1    = (const float*)d_in[3];
    const float* b1v   = (const float*)d_in[4];
    const float* w2    = (const float*)d_in[5];
    float* out = (float*)d_out;
    int P = in_sizes[0] / 32;           // number of flattened problems
    int blocks = (P + 3) / 4;           // 4 problems (warps) per block
    fw_kernel<<<blocks, 128>>>(x_raw, A, b, W1, b1v, w2, out, P);
}

// round 7
// speedup vs baseline: 1.9287x; 1.0806x over previous
#include <cuda_runtime.h>
#include <cuda_bf16.h>
#include <math.h>

namespace {

constexpr int NVc = 32;   // x dim
constexpr int MCc = 24;   // constraint rows in A
constexpr int MHc = 20;   // hard rows
constexpr int ITc = 200;  // ADMM iterations (must match reference trajectory)

// per-warp shared layout (floats)
constexpr int OFF_A = 0;            // A: 24 rows, stride 36
constexpr int OFF_M = 864;          // M workspace: 32 x 36
constexpr int OFF_T = 2160;         // t1 buffer (28)
constexpr int OFF_R = 2192;         // rhs (32, pad 40); also GJ pivot-row buffer
constexpr int OFF_U = 2232;         // x_feas for gradient (32, pad 40)
constexpr int WARPF = 2304;         // 9216 bytes per warp

// Register-resident Gauss-Jordan inverse of SPD 32x32: lane tid owns row tid
// in row[0..31]. buf = 32-float, 16B-aligned smem scratch for pivot broadcast.
// Unified update: f = (row[k] - [tid==k]) * piv  makes the pivot lane's row
// become rk*piv through the same fma as all other lanes.
__device__ __forceinline__ void gj_inv_reg(float row[32], float* buf, int tid) {
#pragma unroll
    for (int k = 0; k < 32; ++k) {
        if (tid == k) {
            float4* b4 = reinterpret_cast<float4*>(buf);
#pragma unroll
            for (int q = 0; q < 8; q++)
                b4[q] = make_float4(row[4 * q], row[4 * q + 1], row[4 * q + 2], row[4 * q + 3]);
        }
        __syncwarp();
        float rk[32];
        {
            const float4* b4 = reinterpret_cast<const float4*>(buf);
#pragma unroll
            for (int q = 0; q < 8; q++) {
                float4 v = b4[q];
                rk[4 * q] = v.x; rk[4 * q + 1] = v.y; rk[4 * q + 2] = v.z; rk[4 * q + 3] = v.w;
            }
        }
        __syncwarp();
        float piv = 1.0f / rk[k];
        float f = (row[k] - ((tid == k) ? 1.0f : 0.0f)) * piv;
#pragma unroll
        for (int j = 0; j < 32; ++j)
            row[j] = fmaf(-f, rk[j], row[j]);
        row[k] = (tid == k) ? piv : -f;
    }
}

__global__ void __launch_bounds__(128, 4)
fw_kernel(const float* __restrict__ x_raw, const float* __restrict__ Ain,
          const float* __restrict__ bin, const float* __restrict__ W1,
          const float* __restrict__ b1v, const float* __restrict__ w2,
          float* __restrict__ out, int P)
{
    __shared__ __align__(16) float smem_all[4 * WARPF];
    const int tid = threadIdx.x & 31;
    const int wid = threadIdx.x >> 5;
    const int p = blockIdx.x * 4 + wid;
    if (p >= P) return;
    float* sw = smem_all + wid * WARPF;

    // ------------------------------------------------------------------
    // Load A (smem rows + register column), b, x_raw
    // ------------------------------------------------------------------
    float Acol[MCc];
    {
        const float* Ap = Ain + (size_t)p * (MCc * NVc);
#pragma unroll
        for (int r = 0; r < MCc; r++) {
            float v = Ap[r * NVc + tid];
            sw[OFF_A + r * 36 + tid] = v;
            Acol[r] = v;
        }
    }
    const float b_own = (tid < MCc) ? bin[(size_t)p * MCc + tid] : 0.0f;
    const float xr = x_raw[(size_t)p * NVc + tid];
    __syncwarp();

    float xf_own = 0.0f, u_own = 0.0f, g_own = 0.0f;

    // ==================================================================
    // Two phases share K-build / GJ / GM-build code:
    //  phase 0: anchor QP (Schur-reduced, Ks = A_h^T A_h + .75 A_s^T A_s + 2I)
    //  phase 1: LMO LP   (K = A^T A + I), preceded by the critic gradient
    // ==================================================================
#pragma unroll 1
    for (int phase = 0; phase < 2; ++phase) {
        if (phase == 1) {
            // ----------------------------------------------------------
            // Gradient of critic: g = W1 @ (w2 * (1 - tanh^2(x W1 + b1)))
            // Single pass: W1 column block kept in regs between fwd + bwd.
            // ----------------------------------------------------------
            float gp[32];
#pragma unroll
            for (int j = 0; j < 32; j++) gp[j] = 0.0f;
#pragma unroll 1
            for (int hb = 0; hb < 8; ++hb) {
                int h = hb * 32 + tid;
                float col[32];
#pragma unroll
                for (int j = 0; j < 32; j++) col[j] = W1[j * 256 + h];
                float z0 = b1v[h], z1 = 0.0f;
                const float4* x4 = reinterpret_cast<const float4*>(sw + OFF_U);
#pragma unroll
                for (int q = 0; q < 8; q++) {
                    float4 xv = x4[q];
                    float s = xv.x * col[4 * q] + xv.y * col[4 * q + 1]
                            + xv.z * col[4 * q + 2] + xv.w * col[4 * q + 3];
                    if (q & 1) z1 += s; else z0 += s;
                }
                float th = tanhf(z0 + z1);
                float v = w2[h] * (1.0f - th * th);
#pragma unroll
                for (int j = 0; j < 32; j++) gp[j] = fmaf(v, col[j], gp[j]);
            }
            // transpose-reduce via the (free) M workspace
            __syncwarp();
            {
                float4* md = reinterpret_cast<float4*>(sw + OFF_M + tid * 36);
#pragma unroll
                for (int q = 0; q < 8; q++)
                    md[q] = make_float4(gp[4 * q], gp[4 * q + 1], gp[4 * q + 2], gp[4 * q + 3]);
            }
            __syncwarp();
            float gs0 = 0.0f, gs1 = 0.0f;
#pragma unroll
            for (int i = 0; i < 32; i++) {
                float v = sw[OFF_M + i * 36 + tid];
                if (i & 1) gs1 += v; else gs0 += v;
            }
            g_own = gs0 + gs1;
            __syncwarp();   // OFF_M reads done before it is overwritten below
        }

        // --------------------------------------------------------------
        // Build K row in registers (diag via init select), invert in regs
        // --------------------------------------------------------------
        float mrow[32];
        {
            const float dg = (phase == 0) ? 2.0f : 1.0f;
            const float ws = (phase == 0) ? 0.75f : 1.0f;
#pragma unroll
            for (int e = 0; e < 32; e++) mrow[e] = (tid == e) ? dg : 0.0f;
#pragma unroll
            for (int r = 0; r < MCc; r++) {
                const float4* ar = reinterpret_cast<const float4*>(sw + OFF_A + r * 36);
                float a = (r >= MHc) ? (Acol[r] * ws) : Acol[r];
#pragma unroll
                for (int q = 0; q < 8; q++) {
                    float4 v = ar[q];
                    mrow[4 * q + 0] = fmaf(a, v.x, mrow[4 * q + 0]);
                    mrow[4 * q + 1] = fmaf(a, v.y, mrow[4 * q + 1]);
                    mrow[4 * q + 2] = fmaf(a, v.z, mrow[4 * q + 2]);
                    mrow[4 * q + 3] = fmaf(a, v.w, mrow[4 * q + 3]);
                }
            }
        }

        gj_inv_reg(mrow, sw + OFF_R, tid);   // mrow = Kinv row tid

        // write Kinv rows to smem once (GM build needs all rows)
        {
            float4* md = reinterpret_cast<float4*>(sw + OFF_M + tid * 36);
#pragma unroll
            for (int q = 0; q < 8; q++)
                md[q] = make_float4(mrow[4 * q], mrow[4 * q + 1], mrow[4 * q + 2], mrow[4 * q + 3]);
        }
        __syncwarp();

        // --------------------------------------------------------------
        // GM row = coef * (A_src * Kinv)
        //  phase 0: coef 1 / 0.75 / -0.25 for rows <20 / <24 / <28; src row
        //           tid (<24) or tid-4 (24..27); lanes 28..31 inactive.
        //  phase 1: coef 1, src tid, lanes <24 active.
        // --------------------------------------------------------------
        float GM[32];
        {
            bool act; float coef; int src;
            if (phase == 0) {
                act = (tid < 28);
                coef = (tid < MHc) ? 1.0f : (tid < MCc) ? 0.75f : -0.25f;
                src = (tid < MCc) ? tid : tid - 4;
            } else {
                act = (tid < MCc);
                coef = 1.0f;
                src = tid;
            }
#pragma unroll
            for (int e = 0; e < 32; e++) GM[e] = 0.0f;
#pragma unroll 1
            for (int jb = 0; jb < 8; jb++) {
                float4 av = make_float4(0.f, 0.f, 0.f, 0.f);
                if (act)
                    av = reinterpret_cast<const float4*>(sw + OFF_A + src * 36)[jb];
                av.x *= coef; av.y *= coef; av.z *= coef; av.w *= coef;
#pragma unroll
                for (int c = 0; c < 4; c++) {
                    int j = 4 * jb + c;
                    float a = (c == 0) ? av.x : (c == 1) ? av.y : (c == 2) ? av.z : av.w;
                    const float4* mrw = reinterpret_cast<const float4*>(sw + OFF_M + j * 36);
#pragma unroll
                    for (int q = 0; q < 8; q++) {
                        float4 v = mrw[q];
                        GM[4 * q + 0] = fmaf(a, v.x, GM[4 * q + 0]);
                        GM[4 * q + 1] = fmaf(a, v.y, GM[4 * q + 1]);
                        GM[4 * q + 2] = fmaf(a, v.z, GM[4 * q + 2]);
                        GM[4 * q + 3] = fmaf(a, v.w, GM[4 * q + 3]);
                    }
                }
            }
        }

        // --------------------------------------------------------------
        // ADMM loops (minv = mrow, register-resident)
        // --------------------------------------------------------------
        if (phase == 0) {
            // Anchor: rows 0..27 (y1,t1) on lanes 0..27; rows 28..59 per-lane
            float y1 = 0.0f, t1o = 0.0f, y3 = 0.0f, t3o = 0.0f;
            u_own = 0.0f;
            const float h1 = (tid < MCc) ? b_own : 0.0f;
            if (tid < 28) sw[OFF_T + tid] = 0.0f;
            float r2_own = 0.0f;
#pragma unroll 1
            for (int it = 0; it <= ITc; ++it) {
                __syncwarp();
                {
                    const float4* t4 = reinterpret_cast<const float4*>(sw + OFF_T);
                    float4 tv0 = t4[0], tv1 = t4[1], tv2 = t4[2], tv3 = t4[3],
                           tv4 = t4[4], tv5 = t4[5], tv6 = t4[6];
                    float r2x = -tv5.x - tv6.x;
                    float r2y = -tv5.y - tv6.y;
                    float r2z = -tv5.z - tv6.z;
                    float r2w = -tv5.w - tv6.w;
                    int k = tid & 3;
                    r2_own = (k == 0) ? r2x : (k == 1) ? r2y : (k == 2) ? r2z : r2w;
                    float a0 = xr, a1 = 0.0f;
                    a0 += Acol[0]  * tv0.x + Acol[1]  * tv0.y + Acol[2]  * tv0.z + Acol[3]  * tv0.w;
                    a1 += Acol[4]  * tv1.x + Acol[5]  * tv1.y + Acol[6]  * tv1.z + Acol[7]  * tv1.w;
                    a0 += Acol[8]  * tv2.x + Acol[9]  * tv2.y + Acol[10] * tv2.z + Acol[11] * tv2.w;
                    a1 += Acol[12] * tv3.x + Acol[13] * tv3.y + Acol[14] * tv3.z + Acol[15] * tv3.w;
                    a0 += Acol[16] * tv4.x + Acol[17] * tv4.y + Acol[18] * tv4.z + Acol[19] * tv4.w;
                    a1 += Acol[20] * (tv5.x + 0.25f * r2x) + Acol[21] * (tv5.y + 0.25f * r2y)
                        + Acol[22] * (tv5.z + 0.25f * r2z) + Acol[23] * (tv5.w + 0.25f * r2w);
                    sw[OFF_R + tid] = a0 + a1 - t3o;
                }
                __syncwarp();
                float gu;
                {
                    const float4* r4 = reinterpret_cast<const float4*>(sw + OFF_R);
                    float a0 = 0.0f, a1 = 0.0f, g0 = 0.0f, g1 = 0.0f;
#pragma unroll
                    for (int q = 0; q < 8; q++) {
                        float4 rv = r4[q];
                        float s = mrow[4 * q] * rv.x + mrow[4 * q + 1] * rv.y
                                + mrow[4 * q + 2] * rv.z + mrow[4 * q + 3] * rv.w;
                        float sg = GM[4 * q] * rv.x + GM[4 * q + 1] * rv.y
                                 + GM[4 * q + 2] * rv.z + GM[4 * q + 3] * rv.w;
                        if (q & 1) { a1 += s; g1 += sg; } else { a0 += s; g0 += sg; }
                    }
                    u_own = a0 + a1;
                    gu = g0 + g1;
                    if (tid >= MHc) gu -= 0.25f * r2_own;
                }
                if (it == ITc) break;
                float w = gu + y1;
                float z = fminf(w, h1);
                y1 = w - z;
                t1o = z - y1;
                if (tid < 28) sw[OFF_T + tid] = t1o;
                float w3 = y3 - u_own;
                float z3 = fminf(w3, 0.0f);
                y3 = w3 - z3;
                t3o = z3 - y3;
            }
            xf_own = u_own;
            sw[OFF_U + tid] = u_own;
            __syncwarp();
        } else {
            // LMO: rows 0..23 (A, h=b) on lanes 0..23; rows 24..55 per-lane
            float y1 = 0.0f, t1o = 0.0f, y3 = 0.0f, t3o = 0.0f;
            u_own = 0.0f;
            if (tid < MCc) sw[OFF_T + tid] = 0.0f;
#pragma unroll 1
            for (int it = 0; it <= ITc; ++it) {
                __syncwarp();
                {
                    const float4* t4 = reinterpret_cast<const float4*>(sw + OFF_T);
                    float4 tv0 = t4[0], tv1 = t4[1], tv2 = t4[2], tv3 = t4[3],
                           tv4 = t4[4], tv5 = t4[5];
                    float a0 = g_own, a1 = 0.0f;
                    a0 += Acol[0]  * tv0.x + Acol[1]  * tv0.y + Acol[2]  * tv0.z + Acol[3]  * tv0.w;
                    a1 += Acol[4]  * tv1.x + Acol[5]  * tv1.y + Acol[6]  * tv1.z + Acol[7]  * tv1.w;
                    a0 += Acol[8]  * tv2.x + Acol[9]  * tv2.y + Acol[10] * tv2.z + Acol[11] * tv2.w;
                    a1 += Acol[12] * tv3.x + Acol[13] * tv3.y + Acol[14] * tv3.z + Acol[15] * tv3.w;
                    a0 += Acol[16] * tv4.x + Acol[17] * tv4.y + Acol[18] * tv4.z + Acol[19] * tv4.w;
                    a1 += Acol[20] * tv5.x + Acol[21] * tv5.y + Acol[22] * tv5.z + Acol[23] * tv5.w;
                    sw[OFF_R + tid] = a0 + a1 - t3o;
                }
                __syncwarp();
                {
                    const float4* r4 = reinterpret_cast<const float4*>(sw + OFF_R);
                    float a0 = 0.0f, a1 = 0.0f, g0 = 0.0f, g1 = 0.0f;
#pragma unroll
                    for (int q = 0; q < 8; q++) {
                        float4 rv = r4[q];
                        float s = mrow[4 * q] * rv.x + mrow[4 * q + 1] * rv.y
                                + mrow[4 * q + 2] * rv.z + mrow[4 * q + 3] * rv.w;
                        float sg = GM[4 * q] * rv.x + GM[4 * q + 1] * rv.y
                                 + GM[4 * q + 2] * rv.z + GM[4 * q + 3] * rv.w;
                        if (q & 1) { a1 += s; g1 += sg; } else { a0 += s; g0 += sg; }
                    }
                    u_own = a0 + a1;
                    float gu = g0 + g1;
                    if (it == ITc) break;
                    float w = gu + y1;
                    float z = fminf(w, b_own);
                    y1 = w - z;
                    t1o = z - y1;
                    if (tid < MCc) sw[OFF_T + tid] = t1o;
                    float w3 = y3 - u_own;
                    float z3 = fminf(w3, 0.0f);
                    y3 = w3 - z3;
                    t3o = z3 - y3;
                }
            }
        }
    }

    // Frank-Wolfe blend
    out[(size_t)p * NVc + tid] = 0.9f * xf_own + 0.1f * u_own;
}

}  // namespace

extern "C" void kernel_launch(void* const* d_in, const int* in_sizes, int n_in,
                              void* d_out, int out_size) {
    const float* x_raw = (const float*)d_in[0];
    const float* A     = (const float*)d_in[1];
    const float* b     = (const float*)d_in[2];
    const float* W1    = (const float*)d_in[3];
    const float* b1v   = (const float*)d_in[4];
    const float* w2    = (const float*)d_in[5];
    float* out = (float*)d_out;
    int P = in_sizes[0] / 32;           // number of flattened problems
    int blocks = (P + 3) / 4;           // 4 problems (warps) per block
    fw_kernel<<<blocks, 128>>>(x_raw, A, b, W1, b1v, w2, out, P);
}

// round 8
// speedup vs baseline: 2.1975x; 1.1394x over previous
#include <cuda_runtime.h>
#include <cuda_bf16.h>
#include <math.h>

namespace {

constexpr int NVc = 32;   // x dim
constexpr int MCc = 24;   // constraint rows in A
constexpr int MHc = 20;   // hard rows
constexpr int ITc = 200;  // ADMM iterations (must match reference trajectory)

// per-warp shared layout (floats)
constexpr int OFF_A = 0;            // A: 24 rows, stride 36
constexpr int OFF_M = 864;          // M workspace: 32 x 36
constexpr int OFF_T = 2160;         // t1 buffer (28)
constexpr int OFF_R = 2192;         // rhs (32, pad 40); also GJ pivot-row buffer
constexpr int OFF_U = 2232;         // x_feas for gradient (32, pad 40)
constexpr int WARPF = 2304;         // 9216 bytes per warp

using ull = unsigned long long;

// ---- packed f32x2 helpers (Blackwell FFMA2 path, PTX-only) ----
__device__ __forceinline__ ull pk2(float lo, float hi) {
    ull r;
    asm("mov.b64 %0, {%1, %2};" : "=l"(r) : "f"(lo), "f"(hi));
    return r;
}
__device__ __forceinline__ float2 upk2(ull v) {
    float lo, hi;
    asm("mov.b64 {%0, %1}, %2;" : "=f"(lo), "=f"(hi) : "l"(v));
    return make_float2(lo, hi);
}
__device__ __forceinline__ ull ffma2(ull a, ull b, ull c) {
    ull d;
    asm("fma.rn.f32x2 %0, %1, %2, %3;" : "=l"(d) : "l"(a), "l"(b), "l"(c));
    return d;
}

// Register-resident Gauss-Jordan inverse of SPD 32x32: lane tid owns row tid.
// buf = 32-float, 16B-aligned smem scratch for pivot-row broadcast.
__device__ __forceinline__ void gj_inv_reg(float row[32], float* buf, int tid) {
#pragma unroll
    for (int k = 0; k < 32; ++k) {
        if (tid == k) {
            float4* b4 = reinterpret_cast<float4*>(buf);
#pragma unroll
            for (int q = 0; q < 8; q++)
                b4[q] = make_float4(row[4 * q], row[4 * q + 1], row[4 * q + 2], row[4 * q + 3]);
        }
        __syncwarp();
        float rk[32];
        {
            const float4* b4 = reinterpret_cast<const float4*>(buf);
#pragma unroll
            for (int q = 0; q < 8; q++) {
                float4 v = b4[q];
                rk[4 * q] = v.x; rk[4 * q + 1] = v.y; rk[4 * q + 2] = v.z; rk[4 * q + 3] = v.w;
            }
        }
        __syncwarp();
        float piv = 1.0f / rk[k];
        float f = (row[k] - ((tid == k) ? 1.0f : 0.0f)) * piv;
#pragma unroll
        for (int j = 0; j < 32; ++j)
            row[j] = fmaf(-f, rk[j], row[j]);
        row[k] = (tid == k) ? piv : -f;
    }
}

__global__ void __launch_bounds__(128, 4)
fw_kernel(const float* __restrict__ x_raw, const float* __restrict__ Ain,
          const float* __restrict__ bin, const float* __restrict__ W1,
          const float* __restrict__ b1v, const float* __restrict__ w2,
          float* __restrict__ out, int P)
{
    __shared__ __align__(16) float smem_all[4 * WARPF];
    const int tid = threadIdx.x & 31;
    const int wid = threadIdx.x >> 5;
    const int p = blockIdx.x * 4 + wid;
    if (p >= P) return;
    float* sw = smem_all + wid * WARPF;

    // ------------------------------------------------------------------
    // Load A (smem rows + packed lane-column apk), b, x_raw
    // ------------------------------------------------------------------
    ull apk[12];   // packed pairs (A[2j][tid], A[2j+1][tid])
    {
        float tmpA[MCc];
        const float* Ap = Ain + (size_t)p * (MCc * NVc);
#pragma unroll
        for (int r = 0; r < MCc; r++) {
            float v = Ap[r * NVc + tid];
            sw[OFF_A + r * 36 + tid] = v;
            tmpA[r] = v;
        }
#pragma unroll
        for (int j = 0; j < 12; j++) apk[j] = pk2(tmpA[2 * j], tmpA[2 * j + 1]);
    }
    const float b_own = (tid < MCc) ? bin[(size_t)p * MCc + tid] : 0.0f;
    const float xr = x_raw[(size_t)p * NVc + tid];
    __syncwarp();

    float xf_own = 0.0f, u_own = 0.0f, g_own = 0.0f;

    // ==================================================================
    //  phase 0: anchor QP (Schur-reduced, Ks = A_h^T A_h + .75 A_s^T A_s + 2I)
    //  phase 1: LMO LP   (K = A^T A + I), preceded by the critic gradient
    // ==================================================================
#pragma unroll 1
    for (int phase = 0; phase < 2; ++phase) {
        if (phase == 1) {
            // ----------------------------------------------------------
            // Gradient of critic: g = W1 @ (w2 * (1 - tanh^2(x W1 + b1)))
            // ----------------------------------------------------------
            float gp[32];
#pragma unroll
            for (int j = 0; j < 32; j++) gp[j] = 0.0f;
#pragma unroll 1
            for (int hb = 0; hb < 8; ++hb) {
                int h = hb * 32 + tid;
                float col[32];
#pragma unroll
                for (int j = 0; j < 32; j++) col[j] = W1[j * 256 + h];
                float z0 = b1v[h], z1 = 0.0f;
                const float4* x4 = reinterpret_cast<const float4*>(sw + OFF_U);
#pragma unroll
                for (int q = 0; q < 8; q++) {
                    float4 xv = x4[q];
                    float s = xv.x * col[4 * q] + xv.y * col[4 * q + 1]
                            + xv.z * col[4 * q + 2] + xv.w * col[4 * q + 3];
                    if (q & 1) z1 += s; else z0 += s;
                }
                float th = tanhf(z0 + z1);
                float v = w2[h] * (1.0f - th * th);
#pragma unroll
                for (int j = 0; j < 32; j++) gp[j] = fmaf(v, col[j], gp[j]);
            }
            __syncwarp();
            {
                float4* md = reinterpret_cast<float4*>(sw + OFF_M + tid * 36);
#pragma unroll
                for (int q = 0; q < 8; q++)
                    md[q] = make_float4(gp[4 * q], gp[4 * q + 1], gp[4 * q + 2], gp[4 * q + 3]);
            }
            __syncwarp();
            float gs0 = 0.0f, gs1 = 0.0f;
#pragma unroll
            for (int i = 0; i < 32; i++) {
                float v = sw[OFF_M + i * 36 + tid];
                if (i & 1) gs1 += v; else gs0 += v;
            }
            g_own = gs0 + gs1;
            __syncwarp();   // OFF_M reads done before it is overwritten below
        }

        // --------------------------------------------------------------
        // Build K row in registers (a read from smem), invert in regs
        // --------------------------------------------------------------
        float mrow[32];
        {
            const float dg = (phase == 0) ? 2.0f : 1.0f;
            const float ws = (phase == 0) ? 0.75f : 1.0f;
#pragma unroll
            for (int e = 0; e < 32; e++) mrow[e] = (tid == e) ? dg : 0.0f;
#pragma unroll
            for (int r = 0; r < MCc; r++) {
                float a = sw[OFF_A + r * 36 + tid];
                if (r >= MHc) a *= ws;
                const float4* ar = reinterpret_cast<const float4*>(sw + OFF_A + r * 36);
#pragma unroll
                for (int q = 0; q < 8; q++) {
                    float4 v = ar[q];
                    mrow[4 * q + 0] = fmaf(a, v.x, mrow[4 * q + 0]);
                    mrow[4 * q + 1] = fmaf(a, v.y, mrow[4 * q + 1]);
                    mrow[4 * q + 2] = fmaf(a, v.z, mrow[4 * q + 2]);
                    mrow[4 * q + 3] = fmaf(a, v.w, mrow[4 * q + 3]);
                }
            }
        }

        gj_inv_reg(mrow, sw + OFF_R, tid);   // mrow = Kinv row tid

        // write Kinv rows to smem once (GM build needs all rows)
        {
            float4* md = reinterpret_cast<float4*>(sw + OFF_M + tid * 36);
#pragma unroll
            for (int q = 0; q < 8; q++)
                md[q] = make_float4(mrow[4 * q], mrow[4 * q + 1], mrow[4 * q + 2], mrow[4 * q + 3]);
        }
        __syncwarp();

        // --------------------------------------------------------------
        // GM row = coef * (A_src * Kinv)
        // --------------------------------------------------------------
        float GM[32];
        {
            bool act; float coef; int src;
            if (phase == 0) {
                act = (tid < 28);
                coef = (tid < MHc) ? 1.0f : (tid < MCc) ? 0.75f : -0.25f;
                src = (tid < MCc) ? tid : tid - 4;
            } else {
                act = (tid < MCc);
                coef = 1.0f;
                src = tid;
            }
#pragma unroll
            for (int e = 0; e < 32; e++) GM[e] = 0.0f;
#pragma unroll 1
            for (int jb = 0; jb < 8; jb++) {
                float4 av = make_float4(0.f, 0.f, 0.f, 0.f);
                if (act)
                    av = reinterpret_cast<const float4*>(sw + OFF_A + src * 36)[jb];
                av.x *= coef; av.y *= coef; av.z *= coef; av.w *= coef;
#pragma unroll
                for (int c = 0; c < 4; c++) {
                    int j = 4 * jb + c;
                    float a = (c == 0) ? av.x : (c == 1) ? av.y : (c == 2) ? av.z : av.w;
                    const float4* mrw = reinterpret_cast<const float4*>(sw + OFF_M + j * 36);
#pragma unroll
                    for (int q = 0; q < 8; q++) {
                        float4 v = mrw[q];
                        GM[4 * q + 0] = fmaf(a, v.x, GM[4 * q + 0]);
                        GM[4 * q + 1] = fmaf(a, v.y, GM[4 * q + 1]);
                        GM[4 * q + 2] = fmaf(a, v.z, GM[4 * q + 2]);
                        GM[4 * q + 3] = fmaf(a, v.w, GM[4 * q + 3]);
                    }
                }
            }
        }

        // pack Kinv row + GM row into f32x2 pairs; scalars die here
        ull mpk[16], gpk[16];
#pragma unroll
        for (int c = 0; c < 16; c++) {
            mpk[c] = pk2(mrow[2 * c], mrow[2 * c + 1]);
            gpk[c] = pk2(GM[2 * c], GM[2 * c + 1]);
        }

        // --------------------------------------------------------------
        // ADMM loops (packed FFMA2 dots)
        // --------------------------------------------------------------
        if (phase == 0) {
            // Anchor: rows 0..27 (y1,t1) on lanes 0..27; rows 28..59 per-lane
            float2 pa = upk2(apk[10]), pb = upk2(apk[11]);
            const float Ac20 = pa.x, Ac21 = pa.y, Ac22 = pb.x, Ac23 = pb.y;
            float y1 = 0.0f, t1o = 0.0f, y3 = 0.0f, t3o = 0.0f;
            u_own = 0.0f;
            const float h1 = (tid < MCc) ? b_own : 0.0f;
            if (tid < 28) sw[OFF_T + tid] = 0.0f;
            float r2_own = 0.0f;
#pragma unroll 1
            for (int it = 0; it <= ITc; ++it) {
                __syncwarp();
                {
                    const ulonglong2* t2 = reinterpret_cast<const ulonglong2*>(sw + OFF_T);
                    ull ac0 = 0ull, ac1 = 0ull;
#pragma unroll
                    for (int q = 0; q < 5; q++) {
                        ulonglong2 tv = t2[q];
                        ac0 = ffma2(apk[2 * q], tv.x, ac0);
                        ac1 = ffma2(apk[2 * q + 1], tv.y, ac1);
                    }
                    const float4* t4 = reinterpret_cast<const float4*>(sw + OFF_T);
                    float4 tv5 = t4[5], tv6 = t4[6];
                    float r2x = -tv5.x - tv6.x;
                    float r2y = -tv5.y - tv6.y;
                    float r2z = -tv5.z - tv6.z;
                    float r2w = -tv5.w - tv6.w;
                    int k = tid & 3;
                    r2_own = (k == 0) ? r2x : (k == 1) ? r2y : (k == 2) ? r2z : r2w;
                    float2 s0 = upk2(ac0), s1 = upk2(ac1);
                    float a0 = xr + s0.x + s0.y + s1.x + s1.y;
                    a0 += Ac20 * (tv5.x + 0.25f * r2x) + Ac21 * (tv5.y + 0.25f * r2y)
                        + Ac22 * (tv5.z + 0.25f * r2z) + Ac23 * (tv5.w + 0.25f * r2w);
                    sw[OFF_R + tid] = a0 - t3o;
                }
                __syncwarp();
                float gu;
                {
                    const ulonglong2* rv2 = reinterpret_cast<const ulonglong2*>(sw + OFF_R);
                    ull au0 = 0ull, au1 = 0ull, ag0 = 0ull, ag1 = 0ull;
#pragma unroll
                    for (int q = 0; q < 8; q++) {
                        ulonglong2 rv = rv2[q];
                        au0 = ffma2(mpk[2 * q], rv.x, au0);
                        au1 = ffma2(mpk[2 * q + 1], rv.y, au1);
                        ag0 = ffma2(gpk[2 * q], rv.x, ag0);
                        ag1 = ffma2(gpk[2 * q + 1], rv.y, ag1);
                    }
                    float2 ua = upk2(au0), ub = upk2(au1), ga = upk2(ag0), gb = upk2(ag1);
                    u_own = ua.x + ua.y + ub.x + ub.y;
                    gu = ga.x + ga.y + gb.x + gb.y;
                    if (tid >= MHc) gu -= 0.25f * r2_own;
                }
                if (it == ITc) break;
                float w = gu + y1;
                float z = fminf(w, h1);
                y1 = w - z;
                t1o = z - y1;
                if (tid < 28) sw[OFF_T + tid] = t1o;
                float w3 = y3 - u_own;
                float z3 = fminf(w3, 0.0f);
                y3 = w3 - z3;
                t3o = z3 - y3;
            }
            xf_own = u_own;
            sw[OFF_U + tid] = u_own;
            __syncwarp();
        } else {
            // LMO: rows 0..23 (A, h=b) on lanes 0..23; rows 24..55 per-lane
            float y1 = 0.0f, t1o = 0.0f, y3 = 0.0f, t3o = 0.0f;
            u_own = 0.0f;
            if (tid < MCc) sw[OFF_T + tid] = 0.0f;
#pragma unroll 1
            for (int it = 0; it <= ITc; ++it) {
                __syncwarp();
                {
                    const ulonglong2* t2 = reinterpret_cast<const ulonglong2*>(sw + OFF_T);
                    ull ac0 = 0ull, ac1 = 0ull;
#pragma unroll
                    for (int q = 0; q < 6; q++) {
                        ulonglong2 tv = t2[q];
                        ac0 = ffma2(apk[2 * q], tv.x, ac0);
                        ac1 = ffma2(apk[2 * q + 1], tv.y, ac1);
                    }
                    float2 s0 = upk2(ac0), s1 = upk2(ac1);
                    sw[OFF_R + tid] = g_own + s0.x + s0.y + s1.x + s1.y - t3o;
                }
                __syncwarp();
                {
                    const ulonglong2* rv2 = reinterpret_cast<const ulonglong2*>(sw + OFF_R);
                    ull au0 = 0ull, au1 = 0ull, ag0 = 0ull, ag1 = 0ull;
#pragma unroll
                    for (int q = 0; q < 8; q++) {
                        ulonglong2 rv = rv2[q];
                        au0 = ffma2(mpk[2 * q], rv.x, au0);
                        au1 = ffma2(mpk[2 * q + 1], rv.y, au1);
                        ag0 = ffma2(gpk[2 * q], rv.x, ag0);
                        ag1 = ffma2(gpk[2 * q + 1], rv.y, ag1);
                    }
                    float2 ua = upk2(au0), ub = upk2(au1), ga = upk2(ag0), gb = upk2(ag1);
                    u_own = ua.x + ua.y + ub.x + ub.y;
                    float gu = ga.x + ga.y + gb.x + gb.y;
                    if (it == ITc) break;
                    float w = gu + y1;
                    float z = fminf(w, b_own);
                    y1 = w - z;
                    t1o = z - y1;
                    if (tid < MCc) sw[OFF_T + tid] = t1o;
                    float w3 = y3 - u_own;
                    float z3 = fminf(w3, 0.0f);
                    y3 = w3 - z3;
                    t3o = z3 - y3;
                }
            }
        }
    }

    // Frank-Wolfe blend
    out[(size_t)p * NVc + tid] = 0.9f * xf_own + 0.1f * u_own;
}

}  // namespace

extern "C" void kernel_launch(void* const* d_in, const int* in_sizes, int n_in,
                              void* d_out, int out_size) {
    const float* x_raw = (const float*)d_in[0];
    const float* A     = (const float*)d_in[1];
    const float* b     = (const float*)d_in[2];
    const float* W1    = (const float*)d_in[3];
    const float* b1v   = (const float*)d_in[4];
    const float* w2    = (const float*)d_in[5];
    float* out = (float*)d_out;
    int P = in_sizes[0] / 32;           // number of flattened problems
    int blocks = (P + 3) / 4;           // 4 problems (warps) per block
    fw_kernel<<<blocks, 128>>>(x_raw, A, b, W1, b1v, w2, out, P);
}